// round 7
// baseline (speedup 1.0000x reference)
#include <cuda_runtime.h>

// ============================================================================
// IEGMNetXNORNew: 5x (quantized conv1d stride2 -> batchnorm(batch stats) ->
// htanh -> quantize) + 2x quantized FC with bn1d.
// Strategy:
//  - quantize weights once per call (prep kernel)
//  - each conv kernel: fuses previous layer's BN+htanh+quantize into its
//    input load, convolves 2 batch elements per lane via packed fma.rn.f32x2,
//    writes raw conv output, accumulates per-channel sum/sumsq (double atomics)
//  - BN scale/shift recomputed redundantly in each consumer kernel's prologue
//    (no separate reduce launches)
// 9 kernel launches total, fully graph-capturable, no allocations.
// ============================================================================

#define BATCH 8192

// ---- scratch (device globals; no allocation allowed) ----
__device__ float  g_bufA[15310848];   // max(B*1869, B*1540, B*740)
__device__ float  g_bufB[12697600];   // max(B*1550, B*1520)
__device__ float  g_z6[BATCH * 10];
__device__ float  g_z7[BATCH * 2];
__device__ float  g_qw[10113];        // quantized weights, packed
__device__ double g_stats[140];       // per-layer (sum, sumsq) pairs

// packed weight offsets
enum { Q1 = 0, Q2 = 18, Q3 = 93, Q4 = 293, Q5 = 1093, QF1 = 2693, QF2 = 10093 };
// stats offsets (doubles, 2 per channel)
enum { S1 = 0, S2 = 6, S3 = 16, S4 = 36, S5 = 76, S6 = 116, S7 = 136 };

__device__ __forceinline__ float qz(float x) {
    // quantize(x, 4): clip to [-1, 0.875], round-half-even to multiples of 1/8
    x = fminf(fmaxf(x, -1.f), 0.875f);
    return rintf(x * 8.f) * 0.125f;
}

__device__ __forceinline__ float2 ffma2(float2 a, float2 b, float2 c) {
    union U { float2 f; unsigned long long u; };
    U ua, ub, uc, ud;
    ua.f = a; ub.f = b; uc.f = c;
    asm("fma.rn.f32x2 %0, %1, %2, %3;" : "=l"(ud.u) : "l"(ua.u), "l"(ub.u), "l"(uc.u));
    return ud.f;
}

// ---- prep: quantize all weights, zero stats ----
__global__ void prep_kernel(const float* __restrict__ w1, const float* __restrict__ w2,
                            const float* __restrict__ w3, const float* __restrict__ w4,
                            const float* __restrict__ w5, const float* __restrict__ fw1,
                            const float* __restrict__ fw2) {
    int i = blockIdx.x * blockDim.x + threadIdx.x;
    if (i < 140) g_stats[i] = 0.0;
    if (i < 10113) {
        float v;
        if      (i < 18)    v = w1[i];
        else if (i < 93)    v = w2[i - 18];
        else if (i < 293)   v = w3[i - 93];
        else if (i < 1093)  v = w4[i - 293];
        else if (i < 2693)  v = w5[i - 1093];
        else if (i < 10093) v = fw1[i - 2693];
        else                v = fw2[i - 10093];
        g_qw[i] = qz(v);
    }
}

// ---- fused conv layer ----
// Block = NS*GDIV*LS threads. Each "stage step" loads NS batch-pairs into
// shared (BN+quant applied), then threads (ps, g, l) compute CG=COUT/GDIV
// output channels at strided positions l for pair ps, two batch elements per
// lane packed in float2 (fma.rn.f32x2).
template <int CIN, int LIN, int COUT, int LOUT, int KS, int NS, int GDIV, int LS, int ITERS>
__global__ void __launch_bounds__(NS * GDIV * LS)
conv_bn_kernel(const float* __restrict__ xin, int in_sel, int out_sel, int qw_off,
               const float* __restrict__ gv, const float* __restrict__ bv,
               int prev_st, double invN, int st_off) {
    constexpr int CG = COUT / GDIV;
    constexpr int CL = CIN * LIN;
    constexpr int NT = NS * GDIV * LS;

    __shared__ float2 s_in[NS][CIN * LIN];
    __shared__ float2 s_w[COUT * CIN * KS];
    __shared__ float  s_aff[2 * CIN];
    __shared__ float  s_sum[COUT], s_sq[COUT];

    const float* in  = (in_sel < 0) ? xin : (in_sel == 0 ? g_bufA : g_bufB);
    float*       out = (out_sel == 0) ? g_bufA : g_bufB;
    const float* qw  = g_qw + qw_off;
    double*      st  = g_stats + st_off;

    int tid = threadIdx.x;
    for (int i = tid; i < COUT * CIN * KS; i += NT) {
        float w = qw[i];
        s_w[i] = make_float2(w, w);
    }
    if (tid < CIN) {
        float sc, sh;
        if (in_sel < 0) { sc = 1.f; sh = 0.f; }
        else {
            double mean = g_stats[prev_st + 2 * tid] * invN;
            double var  = g_stats[prev_st + 2 * tid + 1] * invN - mean * mean;
            double s    = (double)gv[tid] / sqrt(var + 1e-5);
            sc = (float)s;
            sh = (float)((double)bv[tid] - mean * s);
        }
        s_aff[2 * tid]     = sc;
        s_aff[2 * tid + 1] = sh;
    }
    if (tid < COUT) { s_sum[tid] = 0.f; s_sq[tid] = 0.f; }

    const int ps = tid / (GDIV * LS);
    const int g  = (tid / LS) % GDIV;
    const int l0 = tid % LS;

    float lsum[CG], lsq[CG];
#pragma unroll
    for (int j = 0; j < CG; j++) { lsum[j] = 0.f; lsq[j] = 0.f; }

    for (int s = 0; s < ITERS; s++) {
        int pairBase = (blockIdx.x * ITERS + s) * NS;
        __syncthreads();
        // stage: global -> shared with affine+quantize, 2 batch elems per slot
        for (int idx = tid; idx < NS * CL; idx += NT) {
            int pp = idx / CL;
            int e  = idx - pp * CL;
            int c  = e / LIN;
            size_t b0 = (size_t)(pairBase + pp) * 2;
            float sc = s_aff[2 * c], sh = s_aff[2 * c + 1];
            float v0 = qz(fmaf(in[b0 * CL + e], sc, sh));
            float v1 = qz(fmaf(in[(b0 + 1) * CL + e], sc, sh));
            s_in[pp][e] = make_float2(v0, v1);
        }
        __syncthreads();

        size_t b0 = (size_t)(pairBase + ps) * 2;
        float* out0 = out + b0 * (COUT * LOUT);
        float* out1 = out0 + COUT * LOUT;
        for (int l = l0; l < LOUT; l += LS) {
            float2 acc[CG];
#pragma unroll
            for (int j = 0; j < CG; j++) acc[j] = make_float2(0.f, 0.f);
#pragma unroll
            for (int ci = 0; ci < CIN; ci++) {
                float2 v[KS];
#pragma unroll
                for (int k = 0; k < KS; k++) v[k] = s_in[ps][ci * LIN + 2 * l + k];
#pragma unroll
                for (int j = 0; j < CG; j++) {
                    int co = g * CG + j;
#pragma unroll
                    for (int k = 0; k < KS; k++)
                        acc[j] = ffma2(v[k], s_w[(co * CIN + ci) * KS + k], acc[j]);
                }
            }
#pragma unroll
            for (int j = 0; j < CG; j++) {
                int co = g * CG + j;
                out0[co * LOUT + l] = acc[j].x;
                out1[co * LOUT + l] = acc[j].y;
                lsum[j] += acc[j].x + acc[j].y;
                lsq[j]  += acc[j].x * acc[j].x + acc[j].y * acc[j].y;
            }
        }
    }
#pragma unroll
    for (int j = 0; j < CG; j++) {
        atomicAdd(&s_sum[g * CG + j], lsum[j]);
        atomicAdd(&s_sq[g * CG + j], lsq[j]);
    }
    __syncthreads();
    if (tid < COUT) {
        atomicAdd(&st[2 * tid],     (double)s_sum[tid]);
        atomicAdd(&st[2 * tid + 1], (double)s_sq[tid]);
    }
}

// ---- FC1: z6[b][10] = Q(bn5(a5_flat)) @ qfw1^T, + stats ----
__global__ void __launch_bounds__(256)
fc1_kernel(int qw_off, const float* __restrict__ gv, const float* __restrict__ bv,
           int prev_st, double invN, int st_off) {
    __shared__ float  sw[7400];
    __shared__ float2 saff[740];
    __shared__ float2 schan[20];
    __shared__ float  ssum[10], ssq[10];
    int tid = threadIdx.x;
    const float* qw = g_qw + qw_off;
    for (int i = tid; i < 7400; i += 256) {
        int f = i / 10, j = i - f * 10;
        sw[i] = qw[j * 740 + f];
    }
    if (tid < 20) {
        double mean = g_stats[prev_st + 2 * tid] * invN;
        double var  = g_stats[prev_st + 2 * tid + 1] * invN - mean * mean;
        double s    = (double)gv[tid] / sqrt(var + 1e-5);
        schan[tid] = make_float2((float)s, (float)((double)bv[tid] - mean * s));
    }
    if (tid < 10) { ssum[tid] = 0.f; ssq[tid] = 0.f; }
    __syncthreads();
    for (int f = tid; f < 740; f += 256) saff[f] = schan[f / 37];
    __syncthreads();

    int b = blockIdx.x * 256 + tid;
    const float* row = g_bufA + (size_t)b * 740;
    float acc[10];
#pragma unroll
    for (int j = 0; j < 10; j++) acc[j] = 0.f;
    for (int f = 0; f < 740; f += 4) {
        float4 r = *reinterpret_cast<const float4*>(row + f);
        float a0 = qz(fmaf(r.x, saff[f].x,     saff[f].y));
        float a1 = qz(fmaf(r.y, saff[f + 1].x, saff[f + 1].y));
        float a2 = qz(fmaf(r.z, saff[f + 2].x, saff[f + 2].y));
        float a3 = qz(fmaf(r.w, saff[f + 3].x, saff[f + 3].y));
#pragma unroll
        for (int j = 0; j < 10; j++) {
            acc[j] = fmaf(a0, sw[f * 10 + j],       acc[j]);
            acc[j] = fmaf(a1, sw[(f + 1) * 10 + j], acc[j]);
            acc[j] = fmaf(a2, sw[(f + 2) * 10 + j], acc[j]);
            acc[j] = fmaf(a3, sw[(f + 3) * 10 + j], acc[j]);
        }
    }
#pragma unroll
    for (int j = 0; j < 10; j++) {
        g_z6[(size_t)b * 10 + j] = acc[j];
        atomicAdd(&ssum[j], acc[j]);
        atomicAdd(&ssq[j], acc[j] * acc[j]);
    }
    __syncthreads();
    if (tid < 10) {
        atomicAdd(&g_stats[st_off + 2 * tid],     (double)ssum[tid]);
        atomicAdd(&g_stats[st_off + 2 * tid + 1], (double)ssq[tid]);
    }
}

// ---- FC2: z7[b][2] = Q(htanh(bn6(z6))) @ qfw2^T, + stats ----
__global__ void __launch_bounds__(256)
fc2_kernel(int qw_off, const float* __restrict__ gv, const float* __restrict__ bv,
           int prev_st, double invN, int st_off) {
    __shared__ float  sw[20];
    __shared__ float2 saff[10];
    __shared__ float  ssum[2], ssq[2];
    int tid = threadIdx.x;
    if (tid < 20) sw[tid] = g_qw[qw_off + tid];
    if (tid < 10) {
        double mean = g_stats[prev_st + 2 * tid] * invN;
        double var  = g_stats[prev_st + 2 * tid + 1] * invN - mean * mean;
        double s    = (double)gv[tid] / sqrt(var + 1e-5);
        saff[tid] = make_float2((float)s, (float)((double)bv[tid] - mean * s));
    }
    if (tid < 2) { ssum[tid] = 0.f; ssq[tid] = 0.f; }
    __syncthreads();

    int b = blockIdx.x * 256 + tid;
    float a0 = 0.f, a1 = 0.f;
#pragma unroll
    for (int j = 0; j < 10; j++) {
        float a = qz(fmaf(g_z6[(size_t)b * 10 + j], saff[j].x, saff[j].y));
        a0 = fmaf(a, sw[j], a0);
        a1 = fmaf(a, sw[10 + j], a1);
    }
    g_z7[b * 2]     = a0;
    g_z7[b * 2 + 1] = a1;
    atomicAdd(&ssum[0], a0); atomicAdd(&ssq[0], a0 * a0);
    atomicAdd(&ssum[1], a1); atomicAdd(&ssq[1], a1 * a1);
    __syncthreads();
    if (tid < 2) {
        atomicAdd(&g_stats[st_off + 2 * tid],     (double)ssum[tid]);
        atomicAdd(&g_stats[st_off + 2 * tid + 1], (double)ssq[tid]);
    }
}

// ---- final: out = bn7(z7) ----
__global__ void final_kernel(const float* __restrict__ gv, const float* __restrict__ bv,
                             int prev_st, double invN, float* __restrict__ out) {
    int i = blockIdx.x * blockDim.x + threadIdx.x;
    if (i < BATCH * 2) {
        int c = i & 1;
        double mean = g_stats[prev_st + 2 * c] * invN;
        double var  = g_stats[prev_st + 2 * c + 1] * invN - mean * mean;
        double s    = (double)gv[c] / sqrt(var + 1e-5);
        out[i] = (float)(((double)g_z7[i] - mean) * s + (double)bv[c]);
    }
}

extern "C" void kernel_launch(void* const* d_in, const int* in_sizes, int n_in,
                              void* d_out, int out_size) {
    const float* x   = (const float*)d_in[0];
    const float* w1  = (const float*)d_in[1];
    const float* w2  = (const float*)d_in[2];
    const float* w3  = (const float*)d_in[3];
    const float* w4  = (const float*)d_in[4];
    const float* w5  = (const float*)d_in[5];
    const float* fw1 = (const float*)d_in[6];
    const float* fw2 = (const float*)d_in[7];

    // disambiguate g/b ordering: interleaved (g1,b1,g2,b2,...) vs grouped (g1..g7,b1..b7)
    bool inter = (in_sizes[9] == 3);
    const float *gg[7], *bb[7];
    for (int i = 0; i < 7; i++) {
        if (inter) { gg[i] = (const float*)d_in[8 + 2 * i]; bb[i] = (const float*)d_in[9 + 2 * i]; }
        else       { gg[i] = (const float*)d_in[8 + i];     bb[i] = (const float*)d_in[15 + i];    }
    }
    float* out = (float*)d_out;

    const double N1 = 8192.0 * 623.0, N2 = 8192.0 * 310.0, N3 = 8192.0 * 154.0;
    const double N4 = 8192.0 * 76.0,  N5 = 8192.0 * 37.0,  N6 = 8192.0;

    prep_kernel<<<40, 256>>>(w1, w2, w3, w4, w5, fw1, fw2);

    // conv1: x -> bufA (input affine = identity+quantize)
    conv_bn_kernel<1, 1250, 3, 623, 6, 1, 1, 256, 4>
        <<<1024, 256>>>(x, -1, 0, Q1, nullptr, nullptr, 0, 0.0, S1);
    // conv2: bufA -> bufB, input bn from S1/g1/b1
    conv_bn_kernel<3, 623, 5, 310, 5, 2, 1, 128, 2>
        <<<1024, 256>>>(x, 0, 1, Q2, gg[0], bb[0], S1, 1.0 / N1, S2);
    // conv3: bufB -> bufA
    conv_bn_kernel<5, 310, 10, 154, 4, 2, 2, 64, 2>
        <<<1024, 256>>>(x, 1, 0, Q3, gg[1], bb[1], S2, 1.0 / N2, S3);
    // conv4: bufA -> bufB
    conv_bn_kernel<10, 154, 20, 76, 4, 2, 4, 32, 2>
        <<<1024, 256>>>(x, 0, 1, Q4, gg[2], bb[2], S3, 1.0 / N3, S4);
    // conv5: bufB -> bufA
    conv_bn_kernel<20, 76, 20, 37, 4, 2, 4, 32, 2>
        <<<1024, 256>>>(x, 1, 0, Q5, gg[3], bb[3], S4, 1.0 / N4, S5);

    fc1_kernel<<<32, 256>>>(QF1, gg[4], bb[4], S5, 1.0 / N5, S6);
    fc2_kernel<<<32, 256>>>(QF2, gg[5], bb[5], S6, 1.0 / N6, S7);
    final_kernel<<<64, 256>>>(gg[6], bb[6], S7, 1.0 / N6, out);
}

// round 8
// speedup vs baseline: 1.2297x; 1.2297x over previous
#include <cuda_runtime.h>

// ============================================================================
// IEGMNetXNORNew — R7 redesign.
// Layout change: activations stored [B][L][COUT] (channel-contiguous).
// Conv kernels: thread = (batch, TP positions), all COUT channels in regs,
// weights from shared (broadcast LDS), BN+htanh+quantize fused into loads with
// x8 folded into activations and /8 into weights (exact).
// Per-channel batch-norm statistics computed by small separate kernels
// (activations are L2-resident between launches).
// 14 launches, graph-capturable, no allocations.
// ============================================================================

#define BATCH 8192

__device__ __align__(16) float g_bufA[15310848];   // B*1869 max
__device__ __align__(16) float g_bufB[12697600];   // B*1550 max
__device__ __align__(16) float g_z6[BATCH * 10];
__device__ float  g_z7[BATCH * 2];
__device__ float  g_qw[10113];        // quantized weights * 0.125
__device__ double g_stats[140];       // (sum, sumsq) per channel per layer

enum { Q1 = 0, Q2 = 18, Q3 = 93, Q4 = 293, Q5 = 1093, QF1 = 2693, QF2 = 10093 };
enum { S1 = 0, S2 = 6, S3 = 16, S4 = 36, S5 = 76, S6 = 116, S7 = 136 };

__device__ __forceinline__ float qz(float x) {
    x = fminf(fmaxf(x, -1.f), 0.875f);
    return rintf(x * 8.f) * 0.125f;
}
// folded quantizer: returns 8*quantize(x*sc + sh); sc8 = 8*sc, sh8 = 8*sh
__device__ __forceinline__ float q8(float x, float sc8, float sh8) {
    return rintf(fminf(fmaxf(fmaf(x, sc8, sh8), -8.f), 7.f));
}

// ---- prep: quantize all weights (pre-divided by 8), zero stats ----
__global__ void prep_kernel(const float* __restrict__ w1, const float* __restrict__ w2,
                            const float* __restrict__ w3, const float* __restrict__ w4,
                            const float* __restrict__ w5, const float* __restrict__ fw1,
                            const float* __restrict__ fw2) {
    int i = blockIdx.x * blockDim.x + threadIdx.x;
    if (i < 140) g_stats[i] = 0.0;
    if (i < 10113) {
        float v;
        if      (i < 18)    v = w1[i];
        else if (i < 93)    v = w2[i - 18];
        else if (i < 293)   v = w3[i - 93];
        else if (i < 1093)  v = w4[i - 293];
        else if (i < 2693)  v = w5[i - 1093];
        else if (i < 10093) v = fw1[i - 2693];
        else                v = fw2[i - 10093];
        g_qw[i] = qz(v) * 0.125f;
    }
}

// ---- conv layer: input [B][LIN][CIN] -> output [B][LOUT][COUT], stride 2 ----
// Thread computes TP consecutive positions x all COUT channels.
// grid = 32 * TILES blocks of 256 (exactly B*TILES threads).
template <int CIN, int LIN, int COUT, int LOUT, int KS, int TP, int TILES>
__global__ void __launch_bounds__(256)
conv_k(const float* __restrict__ xin, int in_sel, int out_sel, int qw_off,
       const float* __restrict__ gv, const float* __restrict__ bv,
       int prev_st, double invN) {
    __shared__ float  s_w[CIN * KS * COUT];   // [ci][k][co]
    __shared__ float2 s_aff[CIN];

    const float* in  = (in_sel < 0) ? xin : (in_sel == 0 ? g_bufA : g_bufB);
    float*       out = (out_sel == 0) ? g_bufA : g_bufB;
    int tid = threadIdx.x;

    for (int i = tid; i < COUT * CIN * KS; i += 256) {
        int co = i / (CIN * KS);
        int r  = i - co * (CIN * KS);
        int ci = r / KS;
        int k  = r - ci * KS;
        s_w[(ci * KS + k) * COUT + co] = g_qw[qw_off + i];   // OIHW -> [ci][k][co]
    }
    if (tid < CIN) {
        float2 a;
        if (in_sel < 0) a = make_float2(8.f, 0.f);
        else {
            double mean = g_stats[prev_st + 2 * tid] * invN;
            double var  = g_stats[prev_st + 2 * tid + 1] * invN - mean * mean;
            double s    = (double)gv[tid] / sqrt(var + 1e-5);
            a = make_float2((float)(8.0 * s), (float)(8.0 * ((double)bv[tid] - mean * s)));
        }
        s_aff[tid] = a;
    }
    __syncthreads();

    int t = blockIdx.x * 256 + tid;
    int b = t / TILES, tile = t - b * TILES;
    int l0 = tile * TP;
    const float* inb = in + (size_t)b * (LIN * CIN);

    float acc[TP][COUT];
#pragma unroll
    for (int p = 0; p < TP; p++)
#pragma unroll
        for (int co = 0; co < COUT; co++) acc[p][co] = 0.f;

    constexpr int WIN = 2 * TP + KS - 2;
    constexpr int G = (CIN % 4 == 0) ? 4 : ((CIN % 2 == 0) ? 2 : 1);

#pragma unroll
    for (int cg = 0; cg < CIN; cg += G) {
        float2 af[G];
#pragma unroll
        for (int j = 0; j < G; j++) af[j] = s_aff[cg + j];
        float v[G][WIN];
#pragma unroll
        for (int i2 = 0; i2 < WIN; i2++) {
            int pos = 2 * l0 + i2;
            pos = (pos < LIN) ? pos : (LIN - 1);          // tail clamp (value unused)
            const float* pp = inb + (size_t)pos * CIN + cg;
            if (G == 4) {
                float4 x4 = *reinterpret_cast<const float4*>(pp);
                v[0][i2] = q8(x4.x, af[0].x, af[0].y);
                v[1][i2] = q8(x4.y, af[1].x, af[1].y);
                v[2][i2] = q8(x4.z, af[2].x, af[2].y);
                v[3][i2] = q8(x4.w, af[3].x, af[3].y);
            } else if (G == 2) {
                float2 x2 = *reinterpret_cast<const float2*>(pp);
                v[0][i2] = q8(x2.x, af[0].x, af[0].y);
                v[1][i2] = q8(x2.y, af[1].x, af[1].y);
            } else {
                v[0][i2] = q8(*pp, af[0].x, af[0].y);
            }
        }
#pragma unroll
        for (int j = 0; j < G; j++) {
            int ci = cg + j;
#pragma unroll
            for (int k = 0; k < KS; k++) {
#pragma unroll
                for (int co = 0; co < COUT; co++) {
                    float w = s_w[(ci * KS + k) * COUT + co];   // broadcast LDS
#pragma unroll
                    for (int p = 0; p < TP; p++)
                        acc[p][co] = fmaf(v[j][2 * p + k], w, acc[p][co]);
                }
            }
        }
    }

    float* ob = out + (size_t)b * (LOUT * COUT);
#pragma unroll
    for (int p = 0; p < TP; p++) {
        int l = l0 + p;
        if (l < LOUT) {
            if (COUT % 4 == 0) {
#pragma unroll
                for (int q = 0; q < COUT / 4; q++)
                    *reinterpret_cast<float4*>(ob + (size_t)l * COUT + q * 4) =
                        make_float4(acc[p][q * 4], acc[p][q * 4 + 1],
                                    acc[p][q * 4 + 2], acc[p][q * 4 + 3]);
            } else {
#pragma unroll
                for (int co = 0; co < COUT; co++)
                    ob[(size_t)l * COUT + co] = acc[p][co];
            }
        }
    }
}

// ---- per-channel sum/sumsq over [B*L][C] raw activations ----
template <int C, int L>
__global__ void __launch_bounds__(256)
stats_k(int buf_sel, int st_off) {
    const float* a = (buf_sel == 0) ? g_bufA : g_bufB;
    __shared__ float ss[C], sq[C];
    int tid = threadIdx.x;
    if (tid < C) { ss[tid] = 0.f; sq[tid] = 0.f; }
    __syncthreads();
    float ls[C], lq[C];
#pragma unroll
    for (int c = 0; c < C; c++) { ls[c] = 0.f; lq[c] = 0.f; }
    const int R = BATCH * L;
    for (int r = blockIdx.x * 256 + tid; r < R; r += gridDim.x * 256) {
        const float* row = a + (size_t)r * C;
#pragma unroll
        for (int c = 0; c < C; c++) {
            float v = row[c];
            ls[c] += v;
            lq[c] = fmaf(v, v, lq[c]);
        }
    }
#pragma unroll
    for (int c = 0; c < C; c++) { atomicAdd(&ss[c], ls[c]); atomicAdd(&sq[c], lq[c]); }
    __syncthreads();
    if (tid < C) {
        atomicAdd(&g_stats[st_off + 2 * tid],     (double)ss[tid]);
        atomicAdd(&g_stats[st_off + 2 * tid + 1], (double)sq[tid]);
    }
}

// ---- FC1: z6[b][10] = Q(bn5(flatten)) @ qfw1^T ; flatten index c*37+p -> our p*20+c
__global__ void __launch_bounds__(256)
fc1_kernel(const float* __restrict__ gv, const float* __restrict__ bv) {
    __shared__ float  sw[7400];       // [f_local][j]
    __shared__ float2 saff[740];
    __shared__ float2 schan[20];
    __shared__ float  ssum[10], ssq[10];
    int tid = threadIdx.x;
    for (int i = tid; i < 7400; i += 256) {
        int f = i / 10, j = i - f * 10;
        int p = f / 20, c = f - 20 * p;
        sw[i] = g_qw[QF1 + j * 740 + c * 37 + p];
    }
    if (tid < 20) {
        const double invN = 1.0 / (8192.0 * 37.0);
        double mean = g_stats[S5 + 2 * tid] * invN;
        double var  = g_stats[S5 + 2 * tid + 1] * invN - mean * mean;
        double s    = (double)gv[tid] / sqrt(var + 1e-5);
        schan[tid] = make_float2((float)(8.0 * s), (float)(8.0 * ((double)bv[tid] - mean * s)));
    }
    if (tid < 10) { ssum[tid] = 0.f; ssq[tid] = 0.f; }
    __syncthreads();
    for (int f = tid; f < 740; f += 256) saff[f] = schan[f % 20];
    __syncthreads();

    int b = blockIdx.x * 256 + tid;
    const float* row = g_bufA + (size_t)b * 740;
    float acc[10];
#pragma unroll
    for (int j = 0; j < 10; j++) acc[j] = 0.f;
    for (int f = 0; f < 740; f += 4) {
        float4 r = *reinterpret_cast<const float4*>(row + f);
        float a0 = q8(r.x, saff[f].x,     saff[f].y);
        float a1 = q8(r.y, saff[f + 1].x, saff[f + 1].y);
        float a2 = q8(r.z, saff[f + 2].x, saff[f + 2].y);
        float a3 = q8(r.w, saff[f + 3].x, saff[f + 3].y);
#pragma unroll
        for (int j = 0; j < 10; j++) {
            acc[j] = fmaf(a0, sw[f * 10 + j],       acc[j]);
            acc[j] = fmaf(a1, sw[(f + 1) * 10 + j], acc[j]);
            acc[j] = fmaf(a2, sw[(f + 2) * 10 + j], acc[j]);
            acc[j] = fmaf(a3, sw[(f + 3) * 10 + j], acc[j]);
        }
    }
#pragma unroll
    for (int j = 0; j < 10; j++) {
        g_z6[(size_t)b * 10 + j] = acc[j];
        atomicAdd(&ssum[j], acc[j]);
        atomicAdd(&ssq[j], acc[j] * acc[j]);
    }
    __syncthreads();
    if (tid < 10) {
        atomicAdd(&g_stats[S6 + 2 * tid],     (double)ssum[tid]);
        atomicAdd(&g_stats[S6 + 2 * tid + 1], (double)ssq[tid]);
    }
}

// ---- FC2 ----
__global__ void __launch_bounds__(256)
fc2_kernel(const float* __restrict__ gv, const float* __restrict__ bv) {
    __shared__ float  sw[20];
    __shared__ float2 saff[10];
    __shared__ float  ssum[2], ssq[2];
    int tid = threadIdx.x;
    if (tid < 20) sw[tid] = g_qw[QF2 + tid];
    if (tid < 10) {
        const double invN = 1.0 / 8192.0;
        double mean = g_stats[S6 + 2 * tid] * invN;
        double var  = g_stats[S6 + 2 * tid + 1] * invN - mean * mean;
        double s    = (double)gv[tid] / sqrt(var + 1e-5);
        saff[tid] = make_float2((float)(8.0 * s), (float)(8.0 * ((double)bv[tid] - mean * s)));
    }
    if (tid < 2) { ssum[tid] = 0.f; ssq[tid] = 0.f; }
    __syncthreads();

    int b = blockIdx.x * 256 + tid;
    float a0 = 0.f, a1 = 0.f;
#pragma unroll
    for (int j = 0; j < 10; j++) {
        float a = q8(g_z6[(size_t)b * 10 + j], saff[j].x, saff[j].y);
        a0 = fmaf(a, sw[j], a0);
        a1 = fmaf(a, sw[10 + j], a1);
    }
    g_z7[b * 2]     = a0;
    g_z7[b * 2 + 1] = a1;
    atomicAdd(&ssum[0], a0); atomicAdd(&ssq[0], a0 * a0);
    atomicAdd(&ssum[1], a1); atomicAdd(&ssq[1], a1 * a1);
    __syncthreads();
    if (tid < 2) {
        atomicAdd(&g_stats[S7 + 2 * tid],     (double)ssum[tid]);
        atomicAdd(&g_stats[S7 + 2 * tid + 1], (double)ssq[tid]);
    }
}

// ---- final: out = bn7(z7) ----
__global__ void final_kernel(const float* __restrict__ gv, const float* __restrict__ bv,
                             float* __restrict__ out) {
    int i = blockIdx.x * blockDim.x + threadIdx.x;
    if (i < BATCH * 2) {
        int c = i & 1;
        const double invN = 1.0 / 8192.0;
        double mean = g_stats[S7 + 2 * c] * invN;
        double var  = g_stats[S7 + 2 * c + 1] * invN - mean * mean;
        double s    = (double)gv[c] / sqrt(var + 1e-5);
        out[i] = (float)(((double)g_z7[i] - mean) * s + (double)bv[c]);
    }
}

extern "C" void kernel_launch(void* const* d_in, const int* in_sizes, int n_in,
                              void* d_out, int out_size) {
    const float* x   = (const float*)d_in[0];
    const float* w1  = (const float*)d_in[1];
    const float* w2  = (const float*)d_in[2];
    const float* w3  = (const float*)d_in[3];
    const float* w4  = (const float*)d_in[4];
    const float* w5  = (const float*)d_in[5];
    const float* fw1 = (const float*)d_in[6];
    const float* fw2 = (const float*)d_in[7];

    bool inter = (in_sizes[9] == 3);
    const float *gg[7], *bb[7];
    for (int i = 0; i < 7; i++) {
        if (inter) { gg[i] = (const float*)d_in[8 + 2 * i]; bb[i] = (const float*)d_in[9 + 2 * i]; }
        else       { gg[i] = (const float*)d_in[8 + i];     bb[i] = (const float*)d_in[15 + i];    }
    }
    float* out = (float*)d_out;

    const double N1 = 8192.0 * 623.0, N2 = 8192.0 * 310.0, N3 = 8192.0 * 154.0;
    const double N4 = 8192.0 * 76.0;

    prep_kernel<<<40, 256>>>(w1, w2, w3, w4, w5, fw1, fw2);

    // conv1: x[B][1250][1] -> A[B][623][3]
    conv_k<1, 1250, 3, 623, 6, 8, 78><<<32 * 78, 256>>>(x, -1, 0, Q1, nullptr, nullptr, 0, 0.0);
    stats_k<3, 623><<<1184, 256>>>(0, S1);
    // conv2: A -> B[B][310][5]
    conv_k<3, 623, 5, 310, 5, 5, 62><<<32 * 62, 256>>>(x, 0, 1, Q2, gg[0], bb[0], S1, 1.0 / N1);
    stats_k<5, 310><<<1184, 256>>>(1, S2);
    // conv3: B -> A[B][154][10]
    conv_k<5, 310, 10, 154, 4, 4, 39><<<32 * 39, 256>>>(x, 1, 0, Q3, gg[1], bb[1], S2, 1.0 / N2);
    stats_k<10, 154><<<1184, 256>>>(0, S3);
    // conv4: A -> B[B][76][20]
    conv_k<10, 154, 20, 76, 4, 2, 38><<<32 * 38, 256>>>(x, 0, 1, Q4, gg[2], bb[2], S3, 1.0 / N3);
    stats_k<20, 76><<<1184, 256>>>(1, S4);
    // conv5: B -> A[B][37][20]
    conv_k<20, 76, 20, 37, 4, 2, 19><<<32 * 19, 256>>>(x, 1, 0, Q5, gg[3], bb[3], S4, 1.0 / N4);
    stats_k<20, 37><<<1184, 256>>>(0, S5);

    fc1_kernel<<<32, 256>>>(gg[4], bb[4]);
    fc2_kernel<<<32, 256>>>(gg[5], bb[5]);
    final_kernel<<<64, 256>>>(gg[6], bb[6], out);
}

// round 9
// speedup vs baseline: 3.3379x; 2.7144x over previous
#include <cuda_runtime.h>

// ============================================================================
// IEGMNetXNORNew — R8: shared-staged convs (coalesced LDG/STG, conflict-free
// LDS via even/odd position split, TP=3), affine tables precomputed by tiny
// kernels (no doubles in hot kernels), fused stats for conv1/2 (warp shuffle),
// vectorized channel-aligned stats kernels for conv3/4/5.
// ============================================================================

#define BATCH 8192

__device__ __align__(16) float g_bufA[15310848];   // B*1869 max
__device__ __align__(16) float g_bufB[12697600];   // B*1550 max
__device__ __align__(16) float g_z6[BATCH * 10];
__device__ float  g_z7[BATCH * 2];
__device__ float  g_qw[10113];
__device__ double g_stats[140];
__device__ float2 g_aff[6][20];   // per-layer folded BN affine (8*scale, 8*shift)

enum { Q1 = 0, Q2 = 18, Q3 = 93, Q4 = 293, Q5 = 1093, QF1 = 2693, QF2 = 10093 };
enum { S1 = 0, S2 = 6, S3 = 16, S4 = 36, S5 = 76, S6 = 116, S7 = 136 };

__device__ __forceinline__ float qz(float x) {
    x = fminf(fmaxf(x, -1.f), 0.875f);
    return rintf(x * 8.f) * 0.125f;
}
// returns 8*quantize(x*sc+sh) = integer in [-8,7]; sc8=8*sc, sh8=8*sh
__device__ __forceinline__ float q8(float x, float sc8, float sh8) {
    return rintf(fminf(fmaxf(fmaf(x, sc8, sh8), -8.f), 7.f));
}

// ---- prep: quantize weights (/8 folded), zero stats, identity affine ----
__global__ void prep_kernel(const float* __restrict__ w1, const float* __restrict__ w2,
                            const float* __restrict__ w3, const float* __restrict__ w4,
                            const float* __restrict__ w5, const float* __restrict__ fw1,
                            const float* __restrict__ fw2) {
    int i = blockIdx.x * blockDim.x + threadIdx.x;
    if (i == 0) g_aff[0][0] = make_float2(8.f, 0.f);
    if (i < 140) g_stats[i] = 0.0;
    if (i < 10113) {
        float v;
        if      (i < 18)    v = w1[i];
        else if (i < 93)    v = w2[i - 18];
        else if (i < 293)   v = w3[i - 93];
        else if (i < 1093)  v = w4[i - 293];
        else if (i < 2693)  v = w5[i - 1093];
        else if (i < 10093) v = fw1[i - 2693];
        else                v = fw2[i - 10093];
        g_qw[i] = qz(v) * 0.125f;
    }
}

// ---- affine: fold BN(mean,var from stats) + htanh+quantize prescale ----
__global__ void aff_k(int layer, int C, int st_off, double invN,
                      const float* __restrict__ gv, const float* __restrict__ bv) {
    int c = threadIdx.x;
    if (c < C) {
        double mean = g_stats[st_off + 2 * c] * invN;
        double var  = g_stats[st_off + 2 * c + 1] * invN - mean * mean;
        double s    = (double)gv[c] / sqrt(var + 1e-5);
        g_aff[layer][c] = make_float2((float)(8.0 * s),
                                      (float)(8.0 * ((double)bv[c] - mean * s)));
    }
}

// ---- conv: input [B][LIN][CIN] -> output [B][LOUT][COUT], stride 2, VALID ----
template <int CIN, int LIN, int COUT, int LOUT, int KS,
          int NB, int GDIV, int LS, int TP, int PASSES, bool STATS>
__global__ void __launch_bounds__(256, 4)
conv_k(const float* __restrict__ xin, int in_sel, int out_sel,
       int qw_off, int aff_row, int st_off) {
    static_assert(NB * GDIV * LS == 256, "block size");
    constexpr int CG  = COUT / GDIV;
    constexpr int HL  = LIN / 2 + 4;           // padded half-length
    constexpr int LST = LS * TP;
    constexpr int ROW = (COUT & 1) ? COUT : COUT + 1;   // odd row stride
    constexpr int SHE = ((KS - 1) & ~1) / 2;   // max even-tap shift
    constexpr int SHO = ((KS - 2) | 1) / 2;    // max odd-tap shift
    constexpr int VE  = TP + SHE;
    constexpr int VO  = TP + SHO;

    __shared__ float  s_in[NB][CIN][2][HL];
    __shared__ float  s_w[CIN * KS * COUT];
    __shared__ float2 s_aff[CIN];
    __shared__ float  s_out[NB][LST][ROW];
    __shared__ float  s_sum[COUT], s_sq[COUT];

    const float* in  = (in_sel < 0) ? xin : (in_sel == 0 ? g_bufA : g_bufB);
    float*       out = (out_sel == 0) ? g_bufA : g_bufB;
    const int tid = threadIdx.x;

    for (int i = tid; i < COUT * CIN * KS; i += 256) {
        int co = i / (CIN * KS);
        int r  = i - co * (CIN * KS);
        int ci = r / KS, k = r - ci * KS;
        s_w[(ci * KS + k) * COUT + co] = g_qw[qw_off + i];
    }
    if (tid < CIN) s_aff[tid] = g_aff[aff_row][tid];
    if (STATS && tid < COUT) { s_sum[tid] = 0.f; s_sq[tid] = 0.f; }
    __syncthreads();

    // stage input slab (coalesced flat LDG, quantize, even/odd split STS)
    const int b0 = blockIdx.x * NB;
    for (int i = tid; i < NB * LIN * CIN; i += 256) {
        int b = i / (LIN * CIN);
        int e = i - b * (LIN * CIN);
        int l = e / CIN, c = e - l * CIN;
        float2 a = s_aff[c];
        float v = q8(in[(size_t)(b0 + b) * (LIN * CIN) + e], a.x, a.y);
        s_in[b][c][l & 1][l >> 1] = v;
    }
    __syncthreads();

    const int bloc = tid / (GDIV * LS);
    const int g    = (tid / LS) % GDIV;
    const int lidx = tid % LS;

    float lsum[CG], lsq[CG];
#pragma unroll
    for (int j = 0; j < CG; j++) { lsum[j] = 0.f; lsq[j] = 0.f; }

    for (int pass = 0; pass < PASSES; pass++) {
        if (pass) __syncthreads();                 // s_out reuse
        const int lb = pass * LST + lidx * TP;
        const int lr = (lb < LOUT) ? lb : (LOUT - 1);

        float acc[TP][CG];
#pragma unroll
        for (int p = 0; p < TP; p++)
#pragma unroll
            for (int j = 0; j < CG; j++) acc[p][j] = 0.f;

        for (int ci = 0; ci < CIN; ci++) {
            const float* pe = &s_in[bloc][ci][0][lr];
            const float* po = &s_in[bloc][ci][1][lr];
            float ve[VE], vo[VO];
#pragma unroll
            for (int i2 = 0; i2 < VE; i2++) ve[i2] = pe[i2];
#pragma unroll
            for (int i2 = 0; i2 < VO; i2++) vo[i2] = po[i2];
#pragma unroll
            for (int j = 0; j < CG; j++) {
#pragma unroll
                for (int k = 0; k < KS; k++) {
                    float w = s_w[(ci * KS + k) * COUT + g * CG + j];
#pragma unroll
                    for (int p = 0; p < TP; p++) {
                        float tap = (k & 1) ? vo[p + (k >> 1)] : ve[p + (k >> 1)];
                        acc[p][j] = fmaf(tap, w, acc[p][j]);
                    }
                }
            }
        }

#pragma unroll
        for (int p = 0; p < TP; p++) {
            int l = lb + p;
            if (l < LOUT) {
#pragma unroll
                for (int j = 0; j < CG; j++) {
                    float v = acc[p][j];
                    s_out[bloc][lidx * TP + p][g * CG + j] = v;
                    if (STATS) { lsum[j] += v; lsq[j] = fmaf(v, v, lsq[j]); }
                }
            }
        }
        __syncthreads();

        // coalesced store sweep
        const int lpb = pass * LST;
        for (int i = tid; i < NB * LST * COUT; i += 256) {
            int co = i % COUT;
            int t2 = i / COUT;
            int ll = t2 % LST;
            int b  = t2 / LST;
            int l  = lpb + ll;
            if (l < LOUT)
                out[(size_t)(b0 + b) * (LOUT * COUT) + (size_t)l * COUT + co]
                    = s_out[b][ll][co];
        }
    }

    if (STATS) {
        int lane = tid & 31;
#pragma unroll
        for (int j = 0; j < CG; j++) {
            float vs = lsum[j], vq = lsq[j];
#pragma unroll
            for (int o = 16; o > 0; o >>= 1) {
                vs += __shfl_xor_sync(0xffffffffu, vs, o);
                vq += __shfl_xor_sync(0xffffffffu, vq, o);
            }
            if (lane == 0) {
                atomicAdd(&s_sum[g * CG + j], vs);
                atomicAdd(&s_sq[g * CG + j], vq);
            }
        }
        __syncthreads();
        if (tid < COUT) {
            atomicAdd(&g_stats[st_off + 2 * tid],     (double)s_sum[tid]);
            atomicAdd(&g_stats[st_off + 2 * tid + 1], (double)s_sq[tid]);
        }
    }
}

// ---- vectorized per-channel stats over [B*L][C]; V*gridstride % C == 0 ----
template <int C, int L, int V>
__global__ void __launch_bounds__(256)
stats_v(int buf_sel, int st_off) {
    const float* a = (buf_sel == 0) ? g_bufA : g_bufB;
    __shared__ float ss[C], sq[C];
    int tid = threadIdx.x;
    if (tid < C) { ss[tid] = 0.f; sq[tid] = 0.f; }
    __syncthreads();

    const int NV = BATCH * L * C / V;
    const int T  = gridDim.x * 256;           // 1180*256, multiple of 5
    int i0 = blockIdx.x * 256 + tid;
    int c0 = (i0 * V) % C;                    // fixed per thread

    float ls[V], lq[V];
#pragma unroll
    for (int j = 0; j < V; j++) { ls[j] = 0.f; lq[j] = 0.f; }

    for (int i = i0; i < NV; i += T) {
        if (V == 4) {
            float4 r = *reinterpret_cast<const float4*>(a + (size_t)i * 4);
            ls[0] += r.x; lq[0] = fmaf(r.x, r.x, lq[0]);
            ls[1] += r.y; lq[1] = fmaf(r.y, r.y, lq[1]);
            ls[2] += r.z; lq[2] = fmaf(r.z, r.z, lq[2]);
            ls[3] += r.w; lq[3] = fmaf(r.w, r.w, lq[3]);
        } else {
            float2 r = *reinterpret_cast<const float2*>(a + (size_t)i * 2);
            ls[0] += r.x; lq[0] = fmaf(r.x, r.x, lq[0]);
            ls[1] += r.y; lq[1] = fmaf(r.y, r.y, lq[1]);
        }
    }
#pragma unroll
    for (int j = 0; j < V; j++) {
        atomicAdd(&ss[c0 + j], ls[j]);
        atomicAdd(&sq[c0 + j], lq[j]);
    }
    __syncthreads();
    if (tid < C) {
        atomicAdd(&g_stats[st_off + 2 * tid],     (double)ss[tid]);
        atomicAdd(&g_stats[st_off + 2 * tid + 1], (double)sq[tid]);
    }
}

// ---- FC1 ----
__global__ void __launch_bounds__(256)
fc1_kernel() {
    __shared__ float  sw[7400];
    __shared__ float2 saff[740];
    __shared__ float2 schan[20];
    __shared__ float  ssum[10], ssq[10];
    int tid = threadIdx.x;
    for (int i = tid; i < 7400; i += 256) {
        int f = i / 10, j = i - f * 10;
        int p = f / 20, c = f - 20 * p;
        sw[i] = g_qw[QF1 + j * 740 + c * 37 + p];
    }
    if (tid < 20) schan[tid] = g_aff[5][tid];
    if (tid < 10) { ssum[tid] = 0.f; ssq[tid] = 0.f; }
    __syncthreads();
    for (int f = tid; f < 740; f += 256) saff[f] = schan[f % 20];
    __syncthreads();

    int b = blockIdx.x * 256 + tid;
    const float* row = g_bufA + (size_t)b * 740;
    float acc[10];
#pragma unroll
    for (int j = 0; j < 10; j++) acc[j] = 0.f;
    for (int f = 0; f < 740; f += 4) {
        float4 r = *reinterpret_cast<const float4*>(row + f);
        float a0 = q8(r.x, saff[f].x,     saff[f].y);
        float a1 = q8(r.y, saff[f + 1].x, saff[f + 1].y);
        float a2 = q8(r.z, saff[f + 2].x, saff[f + 2].y);
        float a3 = q8(r.w, saff[f + 3].x, saff[f + 3].y);
#pragma unroll
        for (int j = 0; j < 10; j++) {
            acc[j] = fmaf(a0, sw[f * 10 + j],       acc[j]);
            acc[j] = fmaf(a1, sw[(f + 1) * 10 + j], acc[j]);
            acc[j] = fmaf(a2, sw[(f + 2) * 10 + j], acc[j]);
            acc[j] = fmaf(a3, sw[(f + 3) * 10 + j], acc[j]);
        }
    }
#pragma unroll
    for (int j = 0; j < 10; j++) {
        g_z6[(size_t)b * 10 + j] = acc[j];
        atomicAdd(&ssum[j], acc[j]);
        atomicAdd(&ssq[j], acc[j] * acc[j]);
    }
    __syncthreads();
    if (tid < 10) {
        atomicAdd(&g_stats[S6 + 2 * tid],     (double)ssum[tid]);
        atomicAdd(&g_stats[S6 + 2 * tid + 1], (double)ssq[tid]);
    }
}

// ---- FC2 ----
__global__ void __launch_bounds__(256)
fc2_kernel(const float* __restrict__ gv, const float* __restrict__ bv) {
    __shared__ float  sw[20];
    __shared__ float2 saff[10];
    __shared__ float  ssum[2], ssq[2];
    int tid = threadIdx.x;
    if (tid < 20) sw[tid] = g_qw[QF2 + tid];
    if (tid < 10) {
        const double invN = 1.0 / 8192.0;
        double mean = g_stats[S6 + 2 * tid] * invN;
        double var  = g_stats[S6 + 2 * tid + 1] * invN - mean * mean;
        double s    = (double)gv[tid] / sqrt(var + 1e-5);
        saff[tid] = make_float2((float)(8.0 * s), (float)(8.0 * ((double)bv[tid] - mean * s)));
    }
    if (tid < 2) { ssum[tid] = 0.f; ssq[tid] = 0.f; }
    __syncthreads();

    int b = blockIdx.x * 256 + tid;
    float a0 = 0.f, a1 = 0.f;
#pragma unroll
    for (int j = 0; j < 10; j++) {
        float a = q8(g_z6[(size_t)b * 10 + j], saff[j].x, saff[j].y);
        a0 = fmaf(a, sw[j], a0);
        a1 = fmaf(a, sw[10 + j], a1);
    }
    g_z7[b * 2]     = a0;
    g_z7[b * 2 + 1] = a1;
    atomicAdd(&ssum[0], a0); atomicAdd(&ssq[0], a0 * a0);
    atomicAdd(&ssum[1], a1); atomicAdd(&ssq[1], a1 * a1);
    __syncthreads();
    if (tid < 2) {
        atomicAdd(&g_stats[S7 + 2 * tid],     (double)ssum[tid]);
        atomicAdd(&g_stats[S7 + 2 * tid + 1], (double)ssq[tid]);
    }
}

// ---- final: out = bn7(z7) ----
__global__ void final_kernel(const float* __restrict__ gv, const float* __restrict__ bv,
                             float* __restrict__ out) {
    int i = blockIdx.x * blockDim.x + threadIdx.x;
    if (i < BATCH * 2) {
        int c = i & 1;
        const double invN = 1.0 / 8192.0;
        double mean = g_stats[S7 + 2 * c] * invN;
        double var  = g_stats[S7 + 2 * c + 1] * invN - mean * mean;
        double s    = (double)gv[c] / sqrt(var + 1e-5);
        out[i] = (float)(((double)g_z7[i] - mean) * s + (double)bv[c]);
    }
}

extern "C" void kernel_launch(void* const* d_in, const int* in_sizes, int n_in,
                              void* d_out, int out_size) {
    const float* x   = (const float*)d_in[0];
    const float* w1  = (const float*)d_in[1];
    const float* w2  = (const float*)d_in[2];
    const float* w3  = (const float*)d_in[3];
    const float* w4  = (const float*)d_in[4];
    const float* w5  = (const float*)d_in[5];
    const float* fw1 = (const float*)d_in[6];
    const float* fw2 = (const float*)d_in[7];

    bool inter = (in_sizes[9] == 3);
    const float *gg[7], *bb[7];
    for (int i = 0; i < 7; i++) {
        if (inter) { gg[i] = (const float*)d_in[8 + 2 * i]; bb[i] = (const float*)d_in[9 + 2 * i]; }
        else       { gg[i] = (const float*)d_in[8 + i];     bb[i] = (const float*)d_in[15 + i];    }
    }
    float* out = (float*)d_out;

    const double iN1 = 1.0 / (8192.0 * 623.0), iN2 = 1.0 / (8192.0 * 310.0);
    const double iN3 = 1.0 / (8192.0 * 154.0), iN4 = 1.0 / (8192.0 * 76.0);
    const double iN5 = 1.0 / (8192.0 * 37.0);

    prep_kernel<<<40, 256>>>(w1, w2, w3, w4, w5, fw1, fw2);

    // conv1: x[B][1250][1] -> A[B][623][3], fused stats S1
    conv_k<1, 1250, 3, 623, 6, 2, 1, 128, 3, 2, true>
        <<<4096, 256>>>(x, -1, 0, Q1, 0, S1);
    aff_k<<<1, 32>>>(1, 3, S1, iN1, gg[0], bb[0]);

    // conv2: A -> B[B][310][5], fused stats S2
    conv_k<3, 623, 5, 310, 5, 2, 1, 128, 3, 1, true>
        <<<4096, 256>>>(x, 0, 1, Q2, 1, S2);
    aff_k<<<1, 32>>>(2, 5, S2, iN2, gg[1], bb[1]);

    // conv3: B -> A[B][154][10]
    conv_k<5, 310, 10, 154, 4, 2, 2, 64, 3, 1, false>
        <<<4096, 256>>>(x, 1, 0, Q3, 2, 0);
    stats_v<10, 154, 2><<<1180, 256>>>(0, S3);
    aff_k<<<1, 32>>>(3, 10, S3, iN3, gg[2], bb[2]);

    // conv4: A -> B[B][76][20]
    conv_k<10, 154, 20, 76, 4, 2, 4, 32, 3, 1, false>
        <<<4096, 256>>>(x, 0, 1, Q4, 3, 0);
    stats_v<20, 76, 4><<<1180, 256>>>(1, S4);
    aff_k<<<1, 32>>>(4, 20, S4, iN4, gg[3], bb[3]);

    // conv5: B -> A[B][37][20]
    conv_k<20, 76, 20, 37, 4, 4, 4, 16, 3, 1, false>
        <<<2048, 256>>>(x, 1, 0, Q5, 4, 0);
    stats_v<20, 37, 4><<<1180, 256>>>(0, S5);
    aff_k<<<1, 32>>>(5, 20, S5, iN5, gg[4], bb[4]);

    fc1_kernel<<<32, 256>>>();
    fc2_kernel<<<32, 256>>>(gg[5], bb[5]);
    final_kernel<<<64, 256>>>(gg[6], bb[6], out);
}

// round 11
// speedup vs baseline: 6.4959x; 1.9461x over previous
#include <cuda_runtime.h>

// ============================================================================
// IEGMNetXNORNew — R10: R9 design + 16B alignment on vector-accessed shared
// arrays (fixes misaligned-address trap from LDS.64/LDS.128).
// Planar [B][C][Lpad] activations, float4 staging with register affine,
// even/odd split shared arrays, contiguous float4 output sweep,
// conv5 -> transposed [740][B] for coalesced FC1, stats + BN-affine fused.
// 9 launches.
// ============================================================================

#define BATCH 8192

__device__ __align__(16) float g_bufA[15335424];   // B*1872 max
__device__ __align__(16) float g_bufB[12779520];   // B*1560 max
__device__ __align__(16) float g_z6[BATCH * 10];   // [10][B]
__device__ __align__(16) float g_z7[BATCH * 2];    // [2][B]
__device__ float  g_qw[10113];                     // quantized weights /8
__device__ double g_stats[140];

enum { Q1 = 0, Q2 = 18, Q3 = 93, Q4 = 293, Q5 = 1093, QF1 = 2693, QF2 = 10093 };
enum { S1 = 0, S2 = 6, S3 = 16, S4 = 36, S5 = 76, S6 = 116, S7 = 136 };

__device__ __forceinline__ float qz(float x) {
    x = fminf(fmaxf(x, -1.f), 0.875f);
    return rintf(x * 8.f) * 0.125f;
}
// 8*quantize(x*sc+sh): integer in [-8,7]
__device__ __forceinline__ float q8(float x, float sc8, float sh8) {
    return rintf(fminf(fmaxf(fmaf(x, sc8, sh8), -8.f), 7.f));
}

// ---- prep: quantize weights (/8 folded), zero stats ----
__global__ void prep_kernel(const float* __restrict__ w1, const float* __restrict__ w2,
                            const float* __restrict__ w3, const float* __restrict__ w4,
                            const float* __restrict__ w5, const float* __restrict__ fw1,
                            const float* __restrict__ fw2) {
    int i = blockIdx.x * blockDim.x + threadIdx.x;
    if (i < 140) g_stats[i] = 0.0;
    if (i < 10113) {
        float v;
        if      (i < 18)    v = w1[i];
        else if (i < 93)    v = w2[i - 18];
        else if (i < 293)   v = w3[i - 93];
        else if (i < 1093)  v = w4[i - 293];
        else if (i < 2693)  v = w5[i - 1093];
        else if (i < 10093) v = fw1[i - 2693];
        else                v = fw2[i - 10093];
        g_qw[i] = qz(v) * 0.125f;
    }
}

// ---- conv layer: [B][CIN][SLI] -> [B][COUT][SLO] (or FLAT [740][B]) ----
template <int CIN, int SLI, int LIN, int COUT, int LOUT, int SLO, int KS,
          int NB, int GDIV, int LS, int TP, int VST, bool FLAT>
__global__ void __launch_bounds__(256, 4)
conv_k(const float* __restrict__ xin, int in_sel, int out_sel, int qw_off,
       const float* __restrict__ gv, const float* __restrict__ bv,
       int prev_st, double invN, int st_off) {
    static_assert(NB * GDIV * LS == 256, "blk");
    constexpr int CG   = COUT / GDIV;
    constexpr int SH   = KS / 2;
    constexpr int V    = TP + SH;
    constexpr int HL   = (LOUT + TP + SH + 1) & ~1;   // even half-length
    constexpr int FROW = 744;
    constexpr int SBI  = CIN * SLI;
    constexpr int SBO  = COUT * SLO;
    constexpr int FPV  = SLI / VST;

    __shared__ alignas(16) float  s_in[NB * CIN * 2 * HL];
    __shared__ alignas(16) float  s_w[CIN * KS * COUT];
    __shared__ float2 s_aff[CIN];
    __shared__ alignas(16) float  s_out[FLAT ? (NB * FROW) : (NB * COUT * SLO)];
    __shared__ float  s_sum[COUT], s_sq[COUT];

    const float* in  = (in_sel < 0) ? xin : (in_sel == 0 ? g_bufA : g_bufB);
    float*       out = (out_sel == 0) ? g_bufA : g_bufB;
    const int tid = threadIdx.x;

    // weights OIHW -> s_w[(ci*KS+k)*COUT + co]
    for (int i = tid; i < COUT * CIN * KS; i += 256) {
        int co = i / (CIN * KS);
        int r  = i - co * (CIN * KS);
        s_w[r * COUT + co] = g_qw[qw_off + i];
    }
    if (tid < CIN) {
        float2 a;
        if (in_sel < 0) a = make_float2(8.f, 0.f);
        else {
            double mean = g_stats[prev_st + 2 * tid] * invN;
            double var  = g_stats[prev_st + 2 * tid + 1] * invN - mean * mean;
            double s    = (double)gv[tid] / sqrt(var + 1e-5);
            a = make_float2((float)(8.0 * s), (float)(8.0 * ((double)bv[tid] - mean * s)));
        }
        s_aff[tid] = a;
    }
    if (tid < COUT) { s_sum[tid] = 0.f; s_sq[tid] = 0.f; }
    __syncthreads();

    // stage: per-plane vectorized load + quantize + even/odd split
    const int b0 = blockIdx.x * NB;
    for (int i = tid; i < NB * CIN * FPV; i += 256) {
        int pl = i / FPV;
        int r  = i - pl * FPV;
        int c  = pl % CIN;
        int b  = pl / CIN;
        float2 a = s_aff[c];
        const float* src = in + (size_t)(b0 + b) * SBI + c * SLI + r * VST;
        float* de = s_in + pl * 2 * HL;
        if (VST == 4) {
            float4 v = *reinterpret_cast<const float4*>(src);
            *reinterpret_cast<float2*>(de + 2 * r) =
                make_float2(q8(v.x, a.x, a.y), q8(v.z, a.x, a.y));
            *reinterpret_cast<float2*>(de + HL + 2 * r) =
                make_float2(q8(v.y, a.x, a.y), q8(v.w, a.x, a.y));
        } else {
            float2 v = *reinterpret_cast<const float2*>(src);
            de[r]      = q8(v.x, a.x, a.y);
            de[HL + r] = q8(v.y, a.x, a.y);
        }
    }
    __syncthreads();

    const int bloc = tid / (GDIV * LS);
    const int g    = (tid / LS) % GDIV;
    const int lidx = tid % LS;
    const int lb   = lidx * TP;
    const int lr   = (lb < LOUT) ? lb : (LOUT - 1);

    float acc[TP][CG];
#pragma unroll
    for (int p = 0; p < TP; p++)
#pragma unroll
        for (int j = 0; j < CG; j++) acc[p][j] = 0.f;

    const float* pb = s_in + (bloc * CIN) * 2 * HL + lr;
    const float* wp = s_w + g * CG;
    for (int ci = 0; ci < CIN; ci++) {
        float ve[V], vo[V];
#pragma unroll
        for (int i2 = 0; i2 < V; i2++) { ve[i2] = pb[i2]; vo[i2] = pb[HL + i2]; }
#pragma unroll
        for (int k = 0; k < KS; k++) {
            const float* wr = wp + k * COUT;
#pragma unroll
            for (int j = 0; j < CG; j++) {
                float w = wr[j];
#pragma unroll
                for (int p = 0; p < TP; p++) {
                    float tap = (k & 1) ? vo[p + (k >> 1)] : ve[p + (k >> 1)];
                    acc[p][j] = fmaf(tap, w, acc[p][j]);
                }
            }
        }
        pb += 2 * HL;
        wp += KS * COUT;
    }

    float lsum[CG], lsq[CG];
#pragma unroll
    for (int j = 0; j < CG; j++) { lsum[j] = 0.f; lsq[j] = 0.f; }
#pragma unroll
    for (int p = 0; p < TP; p++) {
        int l = lb + p;
        if (l < LOUT) {
#pragma unroll
            for (int j = 0; j < CG; j++) {
                float v = acc[p][j];
                if (FLAT) s_out[bloc * FROW + (g * CG + j) * LOUT + l] = v;
                else      s_out[(bloc * COUT + g * CG + j) * SLO + l] = v;
                lsum[j] += v;
                lsq[j] = fmaf(v, v, lsq[j]);
            }
        }
    }

    // stats: shuffle-reduce within same-(bloc,g) lanes, then shared atomics
    constexpr int W = (LS < 32) ? LS : 32;
#pragma unroll
    for (int j = 0; j < CG; j++) {
        float vs = lsum[j], vq = lsq[j];
#pragma unroll
        for (int o = W / 2; o > 0; o >>= 1) {
            vs += __shfl_xor_sync(0xffffffffu, vs, o);
            vq += __shfl_xor_sync(0xffffffffu, vq, o);
        }
        if ((lidx & (W - 1)) == 0) {
            atomicAdd(&s_sum[g * CG + j], vs);
            atomicAdd(&s_sq[g * CG + j], vq);
        }
    }
    __syncthreads();

    // output sweep
    if (FLAT) {
        for (int i = tid; i < NB * 740; i += 256) {
            int b = i & (NB - 1);
            int f = i / NB;
            out[(size_t)f * BATCH + b0 + b] = s_out[b * FROW + f];
        }
    } else {
        constexpr int OV = NB * COUT * (SLO / 4);
        for (int i = tid; i < OV; i += 256) {
            int b = i / (COUT * (SLO / 4));
            int r = i - b * (COUT * (SLO / 4));
            float4 v = *reinterpret_cast<const float4*>(&s_out[b * SBO + r * 4]);
            *reinterpret_cast<float4*>(&out[(size_t)(b0 + b) * SBO + r * 4]) = v;
        }
    }

    if (tid < COUT) {
        atomicAdd(&g_stats[st_off + 2 * tid],     (double)s_sum[tid]);
        atomicAdd(&g_stats[st_off + 2 * tid + 1], (double)s_sq[tid]);
    }
}

// ---- FC1: z6[j][b] = sum_f Q(bn5) * qw1 ; input [740][B], 256 blocks ----
__global__ void __launch_bounds__(256)
fc1_kernel(const float* __restrict__ gv, const float* __restrict__ bv) {
    __shared__ float  sw[7400];        // [f][j]
    __shared__ float2 saff[740];
    __shared__ float2 schan[20];
    __shared__ float  sp[8][32][10];
    __shared__ float  ssum[10], ssq[10];
    const int tid = threadIdx.x;

    for (int i = tid; i < 7400; i += 256) {
        int f = i / 10, j = i - f * 10;
        sw[i] = g_qw[QF1 + j * 740 + f];
    }
    if (tid < 20) {
        const double invN = 1.0 / (8192.0 * 37.0);
        double mean = g_stats[S5 + 2 * tid] * invN;
        double var  = g_stats[S5 + 2 * tid + 1] * invN - mean * mean;
        double s    = (double)gv[tid] / sqrt(var + 1e-5);
        schan[tid] = make_float2((float)(8.0 * s), (float)(8.0 * ((double)bv[tid] - mean * s)));
    }
    if (tid < 10) { ssum[tid] = 0.f; ssq[tid] = 0.f; }
    __syncthreads();
    for (int f = tid; f < 740; f += 256) saff[f] = schan[f / 37];
    __syncthreads();

    const int bl    = tid & 31;
    const int chunk = tid >> 5;                   // 0..7
    const int b     = blockIdx.x * 32 + bl;
    const int fs = chunk * 92 + (chunk < 4 ? chunk : 4);
    const int fe = fs + (chunk < 4 ? 93 : 92);

    float acc[10];
#pragma unroll
    for (int j = 0; j < 10; j++) acc[j] = 0.f;
    for (int f = fs; f < fe; f++) {
        float2 af = saff[f];
        float a = q8(g_bufA[(size_t)f * BATCH + b], af.x, af.y);
        const float* wr = &sw[f * 10];
#pragma unroll
        for (int j = 0; j < 10; j++) acc[j] = fmaf(a, wr[j], acc[j]);
    }
#pragma unroll
    for (int j = 0; j < 10; j++) sp[chunk][bl][j] = acc[j];
    __syncthreads();

    for (int i = tid; i < 320; i += 256) {
        int b2 = i / 10, j = i - b2 * 10;
        float t = 0.f;
#pragma unroll
        for (int ch = 0; ch < 8; ch++) t += sp[ch][b2][j];
        g_z6[(size_t)j * BATCH + blockIdx.x * 32 + b2] = t;
        atomicAdd(&ssum[j], t);
        atomicAdd(&ssq[j], t * t);
    }
    __syncthreads();
    if (tid < 10) {
        atomicAdd(&g_stats[S6 + 2 * tid],     (double)ssum[tid]);
        atomicAdd(&g_stats[S6 + 2 * tid + 1], (double)ssq[tid]);
    }
}

// ---- FC2: z7[c][b] ----
__global__ void __launch_bounds__(256)
fc2_kernel(const float* __restrict__ gv, const float* __restrict__ bv) {
    __shared__ float  sw[20];
    __shared__ float2 saff[10];
    __shared__ float  ssum[2], ssq[2];
    const int tid = threadIdx.x;
    if (tid < 20) sw[tid] = g_qw[QF2 + tid];
    if (tid < 10) {
        const double invN = 1.0 / 8192.0;
        double mean = g_stats[S6 + 2 * tid] * invN;
        double var  = g_stats[S6 + 2 * tid + 1] * invN - mean * mean;
        double s    = (double)gv[tid] / sqrt(var + 1e-5);
        saff[tid] = make_float2((float)(8.0 * s), (float)(8.0 * ((double)bv[tid] - mean * s)));
    }
    if (tid < 2) { ssum[tid] = 0.f; ssq[tid] = 0.f; }
    __syncthreads();

    const int b = blockIdx.x * 256 + tid;
    float a0 = 0.f, a1 = 0.f;
#pragma unroll
    for (int j = 0; j < 10; j++) {
        float a = q8(g_z6[(size_t)j * BATCH + b], saff[j].x, saff[j].y);
        a0 = fmaf(a, sw[j], a0);
        a1 = fmaf(a, sw[10 + j], a1);
    }
    g_z7[b]         = a0;
    g_z7[BATCH + b] = a1;

    float s0 = a0, q0 = a0 * a0, s1 = a1, q1 = a1 * a1;
#pragma unroll
    for (int o = 16; o > 0; o >>= 1) {
        s0 += __shfl_xor_sync(0xffffffffu, s0, o);
        q0 += __shfl_xor_sync(0xffffffffu, q0, o);
        s1 += __shfl_xor_sync(0xffffffffu, s1, o);
        q1 += __shfl_xor_sync(0xffffffffu, q1, o);
    }
    if ((tid & 31) == 0) {
        atomicAdd(&ssum[0], s0); atomicAdd(&ssq[0], q0);
        atomicAdd(&ssum[1], s1); atomicAdd(&ssq[1], q1);
    }
    __syncthreads();
    if (tid < 2) {
        atomicAdd(&g_stats[S7 + 2 * tid],     (double)ssum[tid]);
        atomicAdd(&g_stats[S7 + 2 * tid + 1], (double)ssq[tid]);
    }
}

// ---- final: out[b][c] = bn7(z7) ----
__global__ void final_kernel(const float* __restrict__ gv, const float* __restrict__ bv,
                             float* __restrict__ out) {
    const int b = blockIdx.x * blockDim.x + threadIdx.x;
    if (b < BATCH) {
        const double invN = 1.0 / 8192.0;
        float o[2];
#pragma unroll
        for (int c = 0; c < 2; c++) {
            double mean = g_stats[S7 + 2 * c] * invN;
            double var  = g_stats[S7 + 2 * c + 1] * invN - mean * mean;
            double s    = (double)gv[c] / sqrt(var + 1e-5);
            o[c] = (float)(((double)g_z7[c * BATCH + b] - mean) * s + (double)bv[c]);
        }
        *reinterpret_cast<float2*>(&out[b * 2]) = make_float2(o[0], o[1]);
    }
}

extern "C" void kernel_launch(void* const* d_in, const int* in_sizes, int n_in,
                              void* d_out, int out_size) {
    const float* x   = (const float*)d_in[0];
    const float* w1  = (const float*)d_in[1];
    const float* w2  = (const float*)d_in[2];
    const float* w3  = (const float*)d_in[3];
    const float* w4  = (const float*)d_in[4];
    const float* w5  = (const float*)d_in[5];
    const float* fw1 = (const float*)d_in[6];
    const float* fw2 = (const float*)d_in[7];

    bool inter = (in_sizes[9] == 3);
    const float *gg[7], *bb[7];
    for (int i = 0; i < 7; i++) {
        if (inter) { gg[i] = (const float*)d_in[8 + 2 * i]; bb[i] = (const float*)d_in[9 + 2 * i]; }
        else       { gg[i] = (const float*)d_in[8 + i];     bb[i] = (const float*)d_in[15 + i];    }
    }
    float* out = (float*)d_out;

    const double iN1 = 1.0 / (8192.0 * 623.0), iN2 = 1.0 / (8192.0 * 310.0);
    const double iN3 = 1.0 / (8192.0 * 154.0), iN4 = 1.0 / (8192.0 * 76.0);

    prep_kernel<<<40, 256>>>(w1, w2, w3, w4, w5, fw1, fw2);

    // conv1: x[B][1][1250] -> A[B][3][624]
    conv_k<1, 1250, 1250, 3, 623, 624, 6, 2, 1, 128, 5, 2, false>
        <<<4096, 256>>>(x, -1, 0, Q1, x, x, 0, 0.0, S1);
    // conv2: A[B][3][624] -> B[B][5][312]
    conv_k<3, 624, 623, 5, 310, 312, 5, 2, 1, 128, 3, 4, false>
        <<<4096, 256>>>(x, 0, 1, Q2, gg[0], bb[0], S1, iN1, S2);
    // conv3: B[B][5][312] -> A[B][10][156]
    conv_k<5, 312, 310, 10, 154, 156, 4, 2, 2, 64, 3, 4, false>
        <<<4096, 256>>>(x, 1, 0, Q3, gg[1], bb[1], S2, iN2, S3);
    // conv4: A[B][10][156] -> B[B][20][76]
    conv_k<10, 156, 154, 20, 76, 76, 4, 2, 4, 32, 3, 4, false>
        <<<4096, 256>>>(x, 0, 1, Q4, gg[2], bb[2], S3, iN3, S4);
    // conv5: B[B][20][76] -> A[740][B] (flat, transposed for FC1)
    conv_k<20, 76, 76, 20, 37, 40, 4, 4, 4, 16, 3, 4, true>
        <<<2048, 256>>>(x, 1, 0, Q5, gg[3], bb[3], S4, iN4, S5);

    fc1_kernel<<<256, 256>>>(gg[4], bb[4]);
    fc2_kernel<<<32, 256>>>(gg[5], bb[5]);
    final_kernel<<<32, 256>>>(gg[6], bb[6], out);
}

// round 12
// speedup vs baseline: 7.3613x; 1.1332x over previous
#include <cuda_runtime.h>

// ============================================================================
// IEGMNetXNORNew — R11: batch-pair packing via fma.rn.f32x2.
// Two batches ride in each float2 shared slot: window LDS.64 loads both,
// weights staged duplicated (w,w), every FFMA2 = 2 MACs. s_in/s_out share one
// union shared buffer. Planar [B][C][SLpad] activations, conv5 -> [740][B].
// 9 launches, graph-capturable, no allocations.
// ============================================================================

#define BATCH 8192

__device__ __align__(16) float g_bufA[15335424];   // B*1872 max
__device__ __align__(16) float g_bufB[12779520];   // B*1560 max
__device__ __align__(16) float g_z6[BATCH * 10];   // [10][B]
__device__ __align__(16) float g_z7[BATCH * 2];    // [2][B]
__device__ float  g_qw[10113];                     // quantized weights /8
__device__ double g_stats[140];

enum { Q1 = 0, Q2 = 18, Q3 = 93, Q4 = 293, Q5 = 1093, QF1 = 2693, QF2 = 10093 };
enum { S1 = 0, S2 = 6, S3 = 16, S4 = 36, S5 = 76, S6 = 116, S7 = 136 };

typedef unsigned long long u64;

__device__ __forceinline__ float qz(float x) {
    x = fminf(fmaxf(x, -1.f), 0.875f);
    return rintf(x * 8.f) * 0.125f;
}
// 8*quantize(x*sc+sh): integer in [-8,7]
__device__ __forceinline__ float q8(float x, float sc8, float sh8) {
    return rintf(fminf(fmaxf(fmaf(x, sc8, sh8), -8.f), 7.f));
}
__device__ __forceinline__ void fma2(u64& d, u64 a, u64 b) {
    asm("fma.rn.f32x2 %0, %1, %2, %0;" : "+l"(d) : "l"(a), "l"(b));
}
__device__ __forceinline__ float2 unpk(u64 v) {
    float2 r;
    asm("mov.b64 {%0, %1}, %2;" : "=f"(r.x), "=f"(r.y) : "l"(v));
    return r;
}

// ---- prep: quantize weights (/8 folded), zero stats ----
__global__ void prep_kernel(const float* __restrict__ w1, const float* __restrict__ w2,
                            const float* __restrict__ w3, const float* __restrict__ w4,
                            const float* __restrict__ w5, const float* __restrict__ fw1,
                            const float* __restrict__ fw2) {
    int i = blockIdx.x * blockDim.x + threadIdx.x;
    if (i < 140) g_stats[i] = 0.0;
    if (i < 10113) {
        float v;
        if      (i < 18)    v = w1[i];
        else if (i < 93)    v = w2[i - 18];
        else if (i < 293)   v = w3[i - 93];
        else if (i < 1093)  v = w4[i - 293];
        else if (i < 2693)  v = w5[i - 1093];
        else if (i < 10093) v = fw1[i - 2693];
        else                v = fw2[i - 10093];
        g_qw[i] = qz(v) * 0.125f;
    }
}

// ---- conv: [B][CIN][SLI] -> [B][COUT][SLO] (or FLAT [740][B]), stride 2 ----
// Block handles 2*NBP batches as NBP float2-packed pairs.
template <int CIN, int SLI, int COUT, int LOUT, int SLO, int KS,
          int NBP, int GDIV, int LS, int TP, int VST, bool FLAT>
__global__ void __launch_bounds__(256, 3)
conv_k(const float* __restrict__ xin, int in_sel, int out_sel, int qw_off,
       const float* __restrict__ gv, const float* __restrict__ bv,
       int prev_st, double invN, int st_off) {
    static_assert(NBP * GDIV * LS == 256, "blk");
    constexpr int CG  = COUT / GDIV;
    constexpr int HL  = SLI / 2;
    constexpr int FROW = 744;
    constexpr int SBI = CIN * SLI;
    constexpr int SBO = COUT * SLO;
    constexpr int FPV = SLI / VST;
    constexpr int VE  = TP + ((KS - 1) >> 1);
    constexpr int VO  = TP + ((KS - 2) >> 1);
    constexpr int SIN_F  = NBP * CIN * 2 * HL * 2;                 // floats
    constexpr int SOUT_F = FLAT ? (NBP * 2 * FROW) : (NBP * 2 * SBO);
    constexpr int UNI_F  = (SIN_F > SOUT_F) ? SIN_F : SOUT_F;

    __shared__ alignas(16) float s_u[UNI_F];
    __shared__ alignas(8)  float2 s_w[CIN * KS * COUT];            // (w,w) dup
    __shared__ float2 s_aff[CIN];
    __shared__ float  s_sum[COUT], s_sq[COUT];

    const float* in  = (in_sel < 0) ? xin : (in_sel == 0 ? g_bufA : g_bufB);
    float*       out = (out_sel == 0) ? g_bufA : g_bufB;
    const int tid = threadIdx.x;

    // weights: OIHW -> s_w[(ci*KS+k)*COUT + co] duplicated
    for (int i = tid; i < CIN * KS * COUT; i += 256) {
        int co = i % COUT, r = i / COUT;
        float w = g_qw[qw_off + co * (CIN * KS) + r];
        s_w[i] = make_float2(w, w);
    }
    if (tid < CIN) {
        float2 a;
        if (in_sel < 0) a = make_float2(8.f, 0.f);
        else {
            double mean = g_stats[prev_st + 2 * tid] * invN;
            double var  = g_stats[prev_st + 2 * tid + 1] * invN - mean * mean;
            double s    = (double)gv[tid] / sqrt(var + 1e-5);
            a = make_float2((float)(8.0 * s), (float)(8.0 * ((double)bv[tid] - mean * s)));
        }
        s_aff[tid] = a;
    }
    if (tid < COUT) { s_sum[tid] = 0.f; s_sq[tid] = 0.f; }
    __syncthreads();

    float2* s2 = reinterpret_cast<float2*>(s_u);
    const int b0 = blockIdx.x * (2 * NBP);

    // stage: two batches per pair, even/odd position split, packed float2
    for (int i = tid; i < NBP * CIN * FPV; i += 256) {
        int pl = i / FPV, r = i - pl * FPV;
        int c  = pl % CIN, pp = pl / CIN;
        float2 a = s_aff[c];
        const float* p0 = in + (size_t)(b0 + 2 * pp) * SBI + c * SLI + r * VST;
        const float* p1 = p0 + SBI;
        float2* de = s2 + ((pp * CIN + c) * 2 + 0) * HL;
        float2* dd = s2 + ((pp * CIN + c) * 2 + 1) * HL;
        if (VST == 4) {
            float4 va = *reinterpret_cast<const float4*>(p0);
            float4 vb = *reinterpret_cast<const float4*>(p1);
            de[2 * r]     = make_float2(q8(va.x, a.x, a.y), q8(vb.x, a.x, a.y));
            dd[2 * r]     = make_float2(q8(va.y, a.x, a.y), q8(vb.y, a.x, a.y));
            de[2 * r + 1] = make_float2(q8(va.z, a.x, a.y), q8(vb.z, a.x, a.y));
            dd[2 * r + 1] = make_float2(q8(va.w, a.x, a.y), q8(vb.w, a.x, a.y));
        } else {
            float2 va = *reinterpret_cast<const float2*>(p0);
            float2 vb = *reinterpret_cast<const float2*>(p1);
            de[r] = make_float2(q8(va.x, a.x, a.y), q8(vb.x, a.x, a.y));
            dd[r] = make_float2(q8(va.y, a.x, a.y), q8(vb.y, a.x, a.y));
        }
    }
    __syncthreads();

    const int pp   = tid / (GDIV * LS);
    const int g    = (tid / LS) % GDIV;
    const int lidx = tid % LS;
    const int lb   = lidx * TP;
    const int lr   = (lb <= LOUT - TP) ? lb : (LOUT - TP);
    const int skip = lb - lr;

    u64 acc[TP][CG];
#pragma unroll
    for (int p = 0; p < TP; p++)
#pragma unroll
        for (int j = 0; j < CG; j++) acc[p][j] = 0ull;

    for (int ci = 0; ci < CIN; ci++) {
        const u64* pe = reinterpret_cast<const u64*>(s2 + ((pp * CIN + ci) * 2 + 0) * HL + lr);
        const u64* po = reinterpret_cast<const u64*>(s2 + ((pp * CIN + ci) * 2 + 1) * HL + lr);
        u64 ve[VE], vo[VO];
#pragma unroll
        for (int i2 = 0; i2 < VE; i2++) ve[i2] = pe[i2];
#pragma unroll
        for (int i2 = 0; i2 < VO; i2++) vo[i2] = po[i2];
        const float2* wb = s_w + ci * KS * COUT + g * CG;
#pragma unroll
        for (int k = 0; k < KS; k++) {
#pragma unroll
            for (int j = 0; j < CG; j++) {
                u64 w = *reinterpret_cast<const u64*>(wb + k * COUT + j);
#pragma unroll
                for (int p = 0; p < TP; p++) {
                    u64 tap = (k & 1) ? vo[p + ((k - 1) >> 1)] : ve[p + (k >> 1)];
                    fma2(acc[p][j], tap, w);
                }
            }
        }
    }
    __syncthreads();   // all s_in reads done; s_u becomes s_out

    float lsum[CG], lsq[CG];
#pragma unroll
    for (int j = 0; j < CG; j++) { lsum[j] = 0.f; lsq[j] = 0.f; }
#pragma unroll
    for (int p = 0; p < TP; p++) {
        if (p >= skip) {
            int l = lr + p;
#pragma unroll
            for (int j = 0; j < CG; j++) {
                float2 v = unpk(acc[p][j]);
                int co = g * CG + j;
                if (FLAT) {
                    s_u[(2 * pp + 0) * FROW + co * LOUT + l] = v.x;
                    s_u[(2 * pp + 1) * FROW + co * LOUT + l] = v.y;
                } else {
                    s_u[((2 * pp + 0) * COUT + co) * SLO + l] = v.x;
                    s_u[((2 * pp + 1) * COUT + co) * SLO + l] = v.y;
                }
                lsum[j] += v.x + v.y;
                lsq[j] = fmaf(v.x, v.x, lsq[j]);
                lsq[j] = fmaf(v.y, v.y, lsq[j]);
            }
        }
    }

    // stats: full-warp shuffle (warp has constant pp,g for LS>=32), lane0 atomics
#pragma unroll
    for (int j = 0; j < CG; j++) {
        float vs = lsum[j], vq = lsq[j];
#pragma unroll
        for (int o = 16; o > 0; o >>= 1) {
            vs += __shfl_xor_sync(0xffffffffu, vs, o);
            vq += __shfl_xor_sync(0xffffffffu, vq, o);
        }
        if ((tid & 31) == 0) {
            atomicAdd(&s_sum[g * CG + j], vs);
            atomicAdd(&s_sq[g * CG + j], vq);
        }
    }
    __syncthreads();

    // coalesced output sweep
    if (FLAT) {
        for (int i = tid; i < NBP * 2 * 740; i += 256) {
            int bb = i % (NBP * 2);
            int f  = i / (NBP * 2);
            out[(size_t)f * BATCH + b0 + bb] = s_u[bb * FROW + f];
        }
    } else {
        constexpr int OV = NBP * 2 * (SBO / 4);
        for (int i = tid; i < OV; i += 256) {
            int bb = i / (SBO / 4);
            int r  = i - bb * (SBO / 4);
            float4 v = *reinterpret_cast<const float4*>(&s_u[bb * SBO + 4 * r]);
            *reinterpret_cast<float4*>(&out[(size_t)(b0 + bb) * SBO + 4 * r]) = v;
        }
    }

    if (tid < COUT) {
        atomicAdd(&g_stats[st_off + 2 * tid],     (double)s_sum[tid]);
        atomicAdd(&g_stats[st_off + 2 * tid + 1], (double)s_sq[tid]);
    }
}

// ---- FC1: z6[j][b], input [740][B] ----
__global__ void __launch_bounds__(256)
fc1_kernel(const float* __restrict__ gv, const float* __restrict__ bv) {
    __shared__ float  sw[7400];        // [f][j]
    __shared__ float2 saff[740];
    __shared__ float2 schan[20];
    __shared__ float  sp[8][32][10];
    __shared__ float  ssum[10], ssq[10];
    const int tid = threadIdx.x;

    for (int i = tid; i < 7400; i += 256) {
        int f = i / 10, j = i - f * 10;
        sw[i] = g_qw[QF1 + j * 740 + f];
    }
    if (tid < 20) {
        const double invN = 1.0 / (8192.0 * 37.0);
        double mean = g_stats[S5 + 2 * tid] * invN;
        double var  = g_stats[S5 + 2 * tid + 1] * invN - mean * mean;
        double s    = (double)gv[tid] / sqrt(var + 1e-5);
        schan[tid] = make_float2((float)(8.0 * s), (float)(8.0 * ((double)bv[tid] - mean * s)));
    }
    if (tid < 10) { ssum[tid] = 0.f; ssq[tid] = 0.f; }
    __syncthreads();
    for (int f = tid; f < 740; f += 256) saff[f] = schan[f / 37];
    __syncthreads();

    const int bl    = tid & 31;
    const int chunk = tid >> 5;
    const int b     = blockIdx.x * 32 + bl;
    const int fs = chunk * 92 + (chunk < 4 ? chunk : 4);
    const int fe = fs + (chunk < 4 ? 93 : 92);

    float acc[10];
#pragma unroll
    for (int j = 0; j < 10; j++) acc[j] = 0.f;
    for (int f = fs; f < fe; f++) {
        float2 af = saff[f];
        float a = q8(g_bufA[(size_t)f * BATCH + b], af.x, af.y);
        const float* wr = &sw[f * 10];
#pragma unroll
        for (int j = 0; j < 10; j++) acc[j] = fmaf(a, wr[j], acc[j]);
    }
#pragma unroll
    for (int j = 0; j < 10; j++) sp[chunk][bl][j] = acc[j];
    __syncthreads();

    for (int i = tid; i < 320; i += 256) {
        int b2 = i / 10, j = i - b2 * 10;
        float t = 0.f;
#pragma unroll
        for (int ch = 0; ch < 8; ch++) t += sp[ch][b2][j];
        g_z6[(size_t)j * BATCH + blockIdx.x * 32 + b2] = t;
        atomicAdd(&ssum[j], t);
        atomicAdd(&ssq[j], t * t);
    }
    __syncthreads();
    if (tid < 10) {
        atomicAdd(&g_stats[S6 + 2 * tid],     (double)ssum[tid]);
        atomicAdd(&g_stats[S6 + 2 * tid + 1], (double)ssq[tid]);
    }
}

// ---- FC2: z7[c][b] ----
__global__ void __launch_bounds__(256)
fc2_kernel(const float* __restrict__ gv, const float* __restrict__ bv) {
    __shared__ float  sw[20];
    __shared__ float2 saff[10];
    __shared__ float  ssum[2], ssq[2];
    const int tid = threadIdx.x;
    if (tid < 20) sw[tid] = g_qw[QF2 + tid];
    if (tid < 10) {
        const double invN = 1.0 / 8192.0;
        double mean = g_stats[S6 + 2 * tid] * invN;
        double var  = g_stats[S6 + 2 * tid + 1] * invN - mean * mean;
        double s    = (double)gv[tid] / sqrt(var + 1e-5);
        saff[tid] = make_float2((float)(8.0 * s), (float)(8.0 * ((double)bv[tid] - mean * s)));
    }
    if (tid < 2) { ssum[tid] = 0.f; ssq[tid] = 0.f; }
    __syncthreads();

    const int b = blockIdx.x * 256 + tid;
    float a0 = 0.f, a1 = 0.f;
#pragma unroll
    for (int j = 0; j < 10; j++) {
        float a = q8(g_z6[(size_t)j * BATCH + b], saff[j].x, saff[j].y);
        a0 = fmaf(a, sw[j], a0);
        a1 = fmaf(a, sw[10 + j], a1);
    }
    g_z7[b]         = a0;
    g_z7[BATCH + b] = a1;

    float s0 = a0, q0 = a0 * a0, s1 = a1, q1 = a1 * a1;
#pragma unroll
    for (int o = 16; o > 0; o >>= 1) {
        s0 += __shfl_xor_sync(0xffffffffu, s0, o);
        q0 += __shfl_xor_sync(0xffffffffu, q0, o);
        s1 += __shfl_xor_sync(0xffffffffu, s1, o);
        q1 += __shfl_xor_sync(0xffffffffu, q1, o);
    }
    if ((tid & 31) == 0) {
        atomicAdd(&ssum[0], s0); atomicAdd(&ssq[0], q0);
        atomicAdd(&ssum[1], s1); atomicAdd(&ssq[1], q1);
    }
    __syncthreads();
    if (tid < 2) {
        atomicAdd(&g_stats[S7 + 2 * tid],     (double)ssum[tid]);
        atomicAdd(&g_stats[S7 + 2 * tid + 1], (double)ssq[tid]);
    }
}

// ---- final: out[b][c] = bn7(z7) ----
__global__ void final_kernel(const float* __restrict__ gv, const float* __restrict__ bv,
                             float* __restrict__ out) {
    const int b = blockIdx.x * blockDim.x + threadIdx.x;
    if (b < BATCH) {
        const double invN = 1.0 / 8192.0;
        float o[2];
#pragma unroll
        for (int c = 0; c < 2; c++) {
            double mean = g_stats[S7 + 2 * c] * invN;
            double var  = g_stats[S7 + 2 * c + 1] * invN - mean * mean;
            double s    = (double)gv[c] / sqrt(var + 1e-5);
            o[c] = (float)(((double)g_z7[c * BATCH + b] - mean) * s + (double)bv[c]);
        }
        *reinterpret_cast<float2*>(&out[b * 2]) = make_float2(o[0], o[1]);
    }
}

extern "C" void kernel_launch(void* const* d_in, const int* in_sizes, int n_in,
                              void* d_out, int out_size) {
    const float* x   = (const float*)d_in[0];
    const float* w1  = (const float*)d_in[1];
    const float* w2  = (const float*)d_in[2];
    const float* w3  = (const float*)d_in[3];
    const float* w4  = (const float*)d_in[4];
    const float* w5  = (const float*)d_in[5];
    const float* fw1 = (const float*)d_in[6];
    const float* fw2 = (const float*)d_in[7];

    bool inter = (in_sizes[9] == 3);
    const float *gg[7], *bb[7];
    for (int i = 0; i < 7; i++) {
        if (inter) { gg[i] = (const float*)d_in[8 + 2 * i]; bb[i] = (const float*)d_in[9 + 2 * i]; }
        else       { gg[i] = (const float*)d_in[8 + i];     bb[i] = (const float*)d_in[15 + i];    }
    }
    float* out = (float*)d_out;

    const double iN1 = 1.0 / (8192.0 * 623.0), iN2 = 1.0 / (8192.0 * 310.0);
    const double iN3 = 1.0 / (8192.0 * 154.0), iN4 = 1.0 / (8192.0 * 76.0);

    prep_kernel<<<40, 256>>>(w1, w2, w3, w4, w5, fw1, fw2);

    // conv1: x[B][1][1250] -> A[B][3][624]
    conv_k<1, 1250, 3, 623, 624, 6, 1, 1, 256, 3, 2, false>
        <<<4096, 256>>>(x, -1, 0, Q1, x, x, 0, 0.0, S1);
    // conv2: A[B][3][624] -> B[B][5][312]
    conv_k<3, 624, 5, 310, 312, 5, 2, 1, 128, 3, 4, false>
        <<<2048, 256>>>(x, 0, 1, Q2, gg[0], bb[0], S1, iN1, S2);
    // conv3: B[B][5][312] -> A[B][10][156]
    conv_k<5, 312, 10, 154, 156, 4, 2, 2, 64, 3, 4, false>
        <<<2048, 256>>>(x, 1, 0, Q3, gg[1], bb[1], S2, iN2, S3);
    // conv4: A[B][10][156] -> B[B][20][76]
    conv_k<10, 156, 20, 76, 76, 4, 2, 4, 32, 3, 4, false>
        <<<2048, 256>>>(x, 0, 1, Q4, gg[2], bb[2], S3, iN3, S4);
    // conv5: B[B][20][76] -> A[740][B] (flat, transposed for FC1)
    conv_k<20, 76, 20, 37, 40, 4, 2, 4, 32, 2, 4, true>
        <<<2048, 256>>>(x, 1, 0, Q5, gg[3], bb[3], S4, iN4, S5);

    fc1_kernel<<<256, 256>>>(gg[4], bb[4]);
    fc2_kernel<<<32, 256>>>(gg[5], bb[5]);
    final_kernel<<<32, 256>>>(gg[6], bb[6], out);
}

// round 13
// speedup vs baseline: 7.7870x; 1.0578x over previous
#include <cuda_runtime.h>

// ============================================================================
// IEGMNetXNORNew — R13: R12 + weight pair-loads (LDS.128 broadcast, [ci][co][k]
// layout), 4 CTAs/SM, STS.128 staging, no-div warp-sliced output sweep.
// Batch-pair fma.rn.f32x2 core, planar [B][C][SLpad], conv5 -> [740][B].
// ============================================================================

#define BATCH 8192

__device__ __align__(16) float g_bufA[15335424];   // B*1872 max
__device__ __align__(16) float g_bufB[12779520];   // B*1560 max
__device__ __align__(16) float g_z6[BATCH * 10];   // [10][B]
__device__ __align__(16) float g_z7[BATCH * 2];    // [2][B]
__device__ float  g_qw[10113];                     // quantized weights /8
__device__ double g_stats[140];

enum { Q1 = 0, Q2 = 18, Q3 = 93, Q4 = 293, Q5 = 1093, QF1 = 2693, QF2 = 10093 };
enum { S1 = 0, S2 = 6, S3 = 16, S4 = 36, S5 = 76, S6 = 116, S7 = 136 };

typedef unsigned long long u64;

__device__ __forceinline__ float qz(float x) {
    x = fminf(fmaxf(x, -1.f), 0.875f);
    return rintf(x * 8.f) * 0.125f;
}
// 8*quantize(x*sc+sh): integer in [-8,7]
__device__ __forceinline__ float q8(float x, float sc8, float sh8) {
    return rintf(fminf(fmaxf(fmaf(x, sc8, sh8), -8.f), 7.f));
}
__device__ __forceinline__ void fma2(u64& d, u64 a, u64 b) {
    asm("fma.rn.f32x2 %0, %1, %2, %0;" : "+l"(d) : "l"(a), "l"(b));
}
__device__ __forceinline__ float2 unpk(u64 v) {
    float2 r;
    asm("mov.b64 {%0, %1}, %2;" : "=f"(r.x), "=f"(r.y) : "l"(v));
    return r;
}

// ---- prep: quantize weights (/8 folded), zero stats ----
__global__ void prep_kernel(const float* __restrict__ w1, const float* __restrict__ w2,
                            const float* __restrict__ w3, const float* __restrict__ w4,
                            const float* __restrict__ w5, const float* __restrict__ fw1,
                            const float* __restrict__ fw2) {
    int i = blockIdx.x * blockDim.x + threadIdx.x;
    if (i < 140) g_stats[i] = 0.0;
    if (i < 10113) {
        float v;
        if      (i < 18)    v = w1[i];
        else if (i < 93)    v = w2[i - 18];
        else if (i < 293)   v = w3[i - 93];
        else if (i < 1093)  v = w4[i - 293];
        else if (i < 2693)  v = w5[i - 1093];
        else if (i < 10093) v = fw1[i - 2693];
        else                v = fw2[i - 10093];
        g_qw[i] = qz(v) * 0.125f;
    }
}

// ---- conv: [B][CIN][SLI] -> [B][COUT][SLO] (or FLAT [740][B]), stride 2 ----
template <int CIN, int SLI, int COUT, int LOUT, int SLO, int KS,
          int NBP, int GDIV, int LS, int TP, int VST, bool FLAT>
__global__ void __launch_bounds__(256, 4)
conv_k(const float* __restrict__ xin, int in_sel, int out_sel, int qw_off,
       const float* __restrict__ gv, const float* __restrict__ bv,
       int prev_st, double invN, int st_off) {
    static_assert(NBP * GDIV * LS == 256, "blk");
    constexpr int CG   = COUT / GDIV;
    constexpr int HL   = SLI / 2;
    constexpr int KSP  = (KS + 1) & ~1;           // even row stride (float2 units)
    constexpr int FROW = 744;
    constexpr int SBI  = CIN * SLI;
    constexpr int SBO  = COUT * SLO;
    constexpr int FPV  = SLI / VST;
    constexpr int VE   = TP + ((KS - 1) >> 1);
    constexpr int VO   = TP + ((KS - 2) >> 1);
    constexpr int SIN_F  = NBP * CIN * 2 * HL * 2;
    constexpr int SOUT_F = FLAT ? (NBP * 2 * FROW) : (NBP * 2 * SBO);
    constexpr int UNI_F  = (SIN_F > SOUT_F) ? SIN_F : SOUT_F;

    __shared__ alignas(16) float  s_u[UNI_F];
    __shared__ alignas(16) float2 s_w[CIN * COUT * KSP];   // [ci][co][k], (w,w)
    __shared__ float2 s_aff[CIN];
    __shared__ float  s_sum[COUT], s_sq[COUT];

    const float* in  = (in_sel < 0) ? xin : (in_sel == 0 ? g_bufA : g_bufB);
    float*       out = (out_sel == 0) ? g_bufA : g_bufB;
    const int tid  = threadIdx.x;
    const int wid  = tid >> 5;
    const int lane = tid & 31;

    // weights: OIHW -> s_w[(ci*COUT+co)*KSP + k], duplicated (w,w); pad zeroed
    for (int i = tid; i < CIN * COUT * KSP; i += 256) {
        int k  = i % KSP;
        int rc = i / KSP;
        int co = rc % COUT, ci = rc / COUT;
        float w = (k < KS) ? g_qw[qw_off + (co * CIN + ci) * KS + k] : 0.f;
        s_w[i] = make_float2(w, w);
    }
    if (tid < CIN) {
        float2 a;
        if (in_sel < 0) a = make_float2(8.f, 0.f);
        else {
            double mean = g_stats[prev_st + 2 * tid] * invN;
            double var  = g_stats[prev_st + 2 * tid + 1] * invN - mean * mean;
            double s    = (double)gv[tid] / sqrt(var + 1e-5);
            a = make_float2((float)(8.0 * s), (float)(8.0 * ((double)bv[tid] - mean * s)));
        }
        s_aff[tid] = a;
    }
    if (tid < COUT) { s_sum[tid] = 0.f; s_sq[tid] = 0.f; }
    __syncthreads();

    float2* s2 = reinterpret_cast<float2*>(s_u);
    const int b0 = blockIdx.x * (2 * NBP);

    // stage: two batches per float2 slot, even/odd split, STS.128 when VST=4
    for (int i = tid; i < NBP * CIN * FPV; i += 256) {
        int pl = i / FPV, r = i - pl * FPV;
        int c  = pl % CIN, pp = pl / CIN;
        float2 a = s_aff[c];
        const float* p0 = in + (size_t)(b0 + 2 * pp) * SBI + c * SLI + r * VST;
        const float* p1 = p0 + SBI;
        float2* de = s2 + ((pp * CIN + c) * 2 + 0) * HL;
        float2* dd = s2 + ((pp * CIN + c) * 2 + 1) * HL;
        if (VST == 4) {
            float4 va = *reinterpret_cast<const float4*>(p0);
            float4 vb = *reinterpret_cast<const float4*>(p1);
            float4 ev = make_float4(q8(va.x, a.x, a.y), q8(vb.x, a.x, a.y),
                                    q8(va.z, a.x, a.y), q8(vb.z, a.x, a.y));
            float4 od = make_float4(q8(va.y, a.x, a.y), q8(vb.y, a.x, a.y),
                                    q8(va.w, a.x, a.y), q8(vb.w, a.x, a.y));
            *reinterpret_cast<float4*>(de + 2 * r) = ev;
            *reinterpret_cast<float4*>(dd + 2 * r) = od;
        } else {
            float2 va = *reinterpret_cast<const float2*>(p0);
            float2 vb = *reinterpret_cast<const float2*>(p1);
            de[r] = make_float2(q8(va.x, a.x, a.y), q8(vb.x, a.x, a.y));
            dd[r] = make_float2(q8(va.y, a.x, a.y), q8(vb.y, a.x, a.y));
        }
    }
    __syncthreads();

    const int pp   = tid / (GDIV * LS);
    const int g    = (tid / LS) % GDIV;
    const int lidx = tid % LS;
    const int lb   = lidx * TP;
    const int lr   = (lb <= LOUT - TP) ? lb : (LOUT - TP);
    const int skip = lb - lr;

    u64 acc[TP][CG];
#pragma unroll
    for (int p = 0; p < TP; p++)
#pragma unroll
        for (int j = 0; j < CG; j++) acc[p][j] = 0ull;

    for (int ci = 0; ci < CIN; ci++) {
        const u64* pe = reinterpret_cast<const u64*>(s2 + ((pp * CIN + ci) * 2 + 0) * HL + lr);
        const u64* po = reinterpret_cast<const u64*>(s2 + ((pp * CIN + ci) * 2 + 1) * HL + lr);
        u64 ve[VE], vo[VO];
#pragma unroll
        for (int i2 = 0; i2 < VE; i2++) ve[i2] = pe[i2];
#pragma unroll
        for (int i2 = 0; i2 < VO; i2++) vo[i2] = po[i2];
        const float2* wr = s_w + (ci * COUT + g * CG) * KSP;
#pragma unroll
        for (int j = 0; j < CG; j++) {
            const float2* wj = wr + j * KSP;
#pragma unroll
            for (int kk = 0; kk < KS / 2; kk++) {
                ulonglong2 wp = *reinterpret_cast<const ulonglong2*>(wj + 2 * kk);
#pragma unroll
                for (int p = 0; p < TP; p++) fma2(acc[p][j], ve[p + kk], wp.x);
#pragma unroll
                for (int p = 0; p < TP; p++) fma2(acc[p][j], vo[p + kk], wp.y);
            }
            if (KS & 1) {
                u64 w = *reinterpret_cast<const u64*>(wj + KS - 1);
#pragma unroll
                for (int p = 0; p < TP; p++)
                    fma2(acc[p][j], ve[p + ((KS - 1) >> 1)], w);
            }
        }
    }
    __syncthreads();   // s_in reads done; s_u becomes s_out

    float lsum[CG], lsq[CG];
#pragma unroll
    for (int j = 0; j < CG; j++) { lsum[j] = 0.f; lsq[j] = 0.f; }
#pragma unroll
    for (int p = 0; p < TP; p++) {
        if (p >= skip) {
            int l = lr + p;
#pragma unroll
            for (int j = 0; j < CG; j++) {
                float2 v = unpk(acc[p][j]);
                int co = g * CG + j;
                if (FLAT) {
                    s_u[(2 * pp + 0) * FROW + co * LOUT + l] = v.x;
                    s_u[(2 * pp + 1) * FROW + co * LOUT + l] = v.y;
                } else {
                    s_u[((2 * pp + 0) * COUT + co) * SLO + l] = v.x;
                    s_u[((2 * pp + 1) * COUT + co) * SLO + l] = v.y;
                }
                lsum[j] += v.x + v.y;
                lsq[j] = fmaf(v.x, v.x, lsq[j]);
                lsq[j] = fmaf(v.y, v.y, lsq[j]);
            }
        }
    }

    // stats: warp has constant (pp,g); shuffle reduce, lane0 shared atomics
#pragma unroll
    for (int j = 0; j < CG; j++) {
        float vs = lsum[j], vq = lsq[j];
#pragma unroll
        for (int o = 16; o > 0; o >>= 1) {
            vs += __shfl_xor_sync(0xffffffffu, vs, o);
            vq += __shfl_xor_sync(0xffffffffu, vq, o);
        }
        if (lane == 0) {
            atomicAdd(&s_sum[g * CG + j], vs);
            atomicAdd(&s_sq[g * CG + j], vq);
        }
    }
    __syncthreads();

    // output sweep
    if (FLAT) {
        for (int i = tid; i < NBP * 2 * 740; i += 256) {
            int bb = i & (NBP * 2 - 1);
            int f  = i / (NBP * 2);
            out[(size_t)f * BATCH + b0 + bb] = s_u[bb * FROW + f];
        }
    } else {
        constexpr int SLABS = NBP * 2;                // 2 or 4
        constexpr int WPS   = 8 / SLABS;              // warps per slab
        const int slab = wid / WPS;
        const int r0   = (wid & (WPS - 1)) * 32 + lane;
        const float4* sv = reinterpret_cast<const float4*>(s_u) + slab * (SBO / 4);
        float4* gp = reinterpret_cast<float4*>(out + (size_t)(b0 + slab) * SBO);
        for (int r = r0; r < SBO / 4; r += WPS * 32) gp[r] = sv[r];
    }

    if (tid < COUT) {
        atomicAdd(&g_stats[st_off + 2 * tid],     (double)s_sum[tid]);
        atomicAdd(&g_stats[st_off + 2 * tid + 1], (double)s_sq[tid]);
    }
}

// ---- FC1: z6[j][b], input [740][B] ----
__global__ void __launch_bounds__(256)
fc1_kernel(const float* __restrict__ gv, const float* __restrict__ bv) {
    __shared__ float  sw[7400];        // [f][j]
    __shared__ float2 saff[740];
    __shared__ float2 schan[20];
    __shared__ float  sp[8][32][10];
    __shared__ float  ssum[10], ssq[10];
    const int tid = threadIdx.x;

    for (int i = tid; i < 7400; i += 256) {
        int f = i / 10, j = i - f * 10;
        sw[i] = g_qw[QF1 + j * 740 + f];
    }
    if (tid < 20) {
        const double invN = 1.0 / (8192.0 * 37.0);
        double mean = g_stats[S5 + 2 * tid] * invN;
        double var  = g_stats[S5 + 2 * tid + 1] * invN - mean * mean;
        double s    = (double)gv[tid] / sqrt(var + 1e-5);
        schan[tid] = make_float2((float)(8.0 * s), (float)(8.0 * ((double)bv[tid] - mean * s)));
    }
    if (tid < 10) { ssum[tid] = 0.f; ssq[tid] = 0.f; }
    __syncthreads();
    for (int f = tid; f < 740; f += 256) saff[f] = schan[f / 37];
    __syncthreads();

    const int bl    = tid & 31;
    const int chunk = tid >> 5;
    const int b     = blockIdx.x * 32 + bl;
    const int fs = chunk * 92 + (chunk < 4 ? chunk : 4);
    const int fe = fs + (chunk < 4 ? 93 : 92);

    float acc[10];
#pragma unroll
    for (int j = 0; j < 10; j++) acc[j] = 0.f;
    for (int f = fs; f < fe; f++) {
        float2 af = saff[f];
        float a = q8(g_bufA[(size_t)f * BATCH + b], af.x, af.y);
        const float* wr = &sw[f * 10];
#pragma unroll
        for (int j = 0; j < 10; j++) acc[j] = fmaf(a, wr[j], acc[j]);
    }
#pragma unroll
    for (int j = 0; j < 10; j++) sp[chunk][bl][j] = acc[j];
    __syncthreads();

    for (int i = tid; i < 320; i += 256) {
        int b2 = i / 10, j = i - b2 * 10;
        float t = 0.f;
#pragma unroll
        for (int ch = 0; ch < 8; ch++) t += sp[ch][b2][j];
        g_z6[(size_t)j * BATCH + blockIdx.x * 32 + b2] = t;
        atomicAdd(&ssum[j], t);
        atomicAdd(&ssq[j], t * t);
    }
    __syncthreads();
    if (tid < 10) {
        atomicAdd(&g_stats[S6 + 2 * tid],     (double)ssum[tid]);
        atomicAdd(&g_stats[S6 + 2 * tid + 1], (double)ssq[tid]);
    }
}

// ---- FC2: z7[c][b] ----
__global__ void __launch_bounds__(256)
fc2_kernel(const float* __restrict__ gv, const float* __restrict__ bv) {
    __shared__ float  sw[20];
    __shared__ float2 saff[10];
    __shared__ float  ssum[2], ssq[2];
    const int tid = threadIdx.x;
    if (tid < 20) sw[tid] = g_qw[QF2 + tid];
    if (tid < 10) {
        const double invN = 1.0 / 8192.0;
        double mean = g_stats[S6 + 2 * tid] * invN;
        double var  = g_stats[S6 + 2 * tid + 1] * invN - mean * mean;
        double s    = (double)gv[tid] / sqrt(var + 1e-5);
        saff[tid] = make_float2((float)(8.0 * s), (float)(8.0 * ((double)bv[tid] - mean * s)));
    }
    if (tid < 2) { ssum[tid] = 0.f; ssq[tid] = 0.f; }
    __syncthreads();

    const int b = blockIdx.x * 256 + tid;
    float a0 = 0.f, a1 = 0.f;
#pragma unroll
    for (int j = 0; j < 10; j++) {
        float a = q8(g_z6[(size_t)j * BATCH + b], saff[j].x, saff[j].y);
        a0 = fmaf(a, sw[j], a0);
        a1 = fmaf(a, sw[10 + j], a1);
    }
    g_z7[b]         = a0;
    g_z7[BATCH + b] = a1;

    float s0 = a0, q0 = a0 * a0, s1 = a1, q1 = a1 * a1;
#pragma unroll
    for (int o = 16; o > 0; o >>= 1) {
        s0 += __shfl_xor_sync(0xffffffffu, s0, o);
        q0 += __shfl_xor_sync(0xffffffffu, q0, o);
        s1 += __shfl_xor_sync(0xffffffffu, s1, o);
        q1 += __shfl_xor_sync(0xffffffffu, q1, o);
    }
    if ((tid & 31) == 0) {
        atomicAdd(&ssum[0], s0); atomicAdd(&ssq[0], q0);
        atomicAdd(&ssum[1], s1); atomicAdd(&ssq[1], q1);
    }
    __syncthreads();
    if (tid < 2) {
        atomicAdd(&g_stats[S7 + 2 * tid],     (double)ssum[tid]);
        atomicAdd(&g_stats[S7 + 2 * tid + 1], (double)ssq[tid]);
    }
}

// ---- final: out[b][c] = bn7(z7) ----
__global__ void final_kernel(const float* __restrict__ gv, const float* __restrict__ bv,
                             float* __restrict__ out) {
    const int b = blockIdx.x * blockDim.x + threadIdx.x;
    if (b < BATCH) {
        const double invN = 1.0 / 8192.0;
        float o[2];
#pragma unroll
        for (int c = 0; c < 2; c++) {
            double mean = g_stats[S7 + 2 * c] * invN;
            double var  = g_stats[S7 + 2 * c + 1] * invN - mean * mean;
            double s    = (double)gv[c] / sqrt(var + 1e-5);
            o[c] = (float)(((double)g_z7[c * BATCH + b] - mean) * s + (double)bv[c]);
        }
        *reinterpret_cast<float2*>(&out[b * 2]) = make_float2(o[0], o[1]);
    }
}

extern "C" void kernel_launch(void* const* d_in, const int* in_sizes, int n_in,
                              void* d_out, int out_size) {
    const float* x   = (const float*)d_in[0];
    const float* w1  = (const float*)d_in[1];
    const float* w2  = (const float*)d_in[2];
    const float* w3  = (const float*)d_in[3];
    const float* w4  = (const float*)d_in[4];
    const float* w5  = (const float*)d_in[5];
    const float* fw1 = (const float*)d_in[6];
    const float* fw2 = (const float*)d_in[7];

    bool inter = (in_sizes[9] == 3);
    const float *gg[7], *bb[7];
    for (int i = 0; i < 7; i++) {
        if (inter) { gg[i] = (const float*)d_in[8 + 2 * i]; bb[i] = (const float*)d_in[9 + 2 * i]; }
        else       { gg[i] = (const float*)d_in[8 + i];     bb[i] = (const float*)d_in[15 + i];    }
    }
    float* out = (float*)d_out;

    const double iN1 = 1.0 / (8192.0 * 623.0), iN2 = 1.0 / (8192.0 * 310.0);
    const double iN3 = 1.0 / (8192.0 * 154.0), iN4 = 1.0 / (8192.0 * 76.0);

    prep_kernel<<<40, 256>>>(w1, w2, w3, w4, w5, fw1, fw2);

    // conv1: x[B][1][1250] -> A[B][3][624]
    conv_k<1, 1250, 3, 623, 624, 6, 1, 1, 256, 3, 2, false>
        <<<4096, 256>>>(x, -1, 0, Q1, x, x, 0, 0.0, S1);
    // conv2: A[B][3][624] -> B[B][5][312]
    conv_k<3, 624, 5, 310, 312, 5, 2, 1, 128, 3, 4, false>
        <<<2048, 256>>>(x, 0, 1, Q2, gg[0], bb[0], S1, iN1, S2);
    // conv3: B[B][5][312] -> A[B][10][156]
    conv_k<5, 312, 10, 154, 156, 4, 2, 2, 64, 3, 4, false>
        <<<2048, 256>>>(x, 1, 0, Q3, gg[1], bb[1], S2, iN2, S3);
    // conv4: A[B][10][156] -> B[B][20][76]
    conv_k<10, 156, 20, 76, 76, 4, 2, 4, 32, 3, 4, false>
        <<<2048, 256>>>(x, 0, 1, Q4, gg[2], bb[2], S3, iN3, S4);
    // conv5: B[B][20][76] -> A[740][B] (flat, transposed for FC1)
    conv_k<20, 76, 20, 37, 40, 4, 2, 4, 32, 2, 4, true>
        <<<2048, 256>>>(x, 1, 0, Q5, gg[3], bb[3], S4, iN4, S5);

    fc1_kernel<<<256, 256>>>(gg[4], bb[4]);
    fc2_kernel<<<32, 256>>>(gg[5], bb[5]);
    final_kernel<<<32, 256>>>(gg[6], bb[6], out);
}

// round 16
// speedup vs baseline: 9.1563x; 1.1758x over previous
#include <cuda_runtime.h>

// ============================================================================
// IEGMNetXNORNew — R15: dp4a integer conv core (fixed __dp4a overload via int
// casts). Inputs staged as packed s8 (1 byte/position per channel plane);
// stride-2 KS<=4 window = one 32-bit word (odd positions via byte_perm);
// __dp4a = 4 exact MACs/slot. Conv outputs stored as float(acc) = 64*conv;
// /64 folded into consumer BN affines.
// ============================================================================

#define BATCH 8192

__device__ __align__(16) float g_bufA[15335424];   // B*1872 max
__device__ __align__(16) float g_bufB[12779520];   // B*1560 max
__device__ __align__(16) float g_z6[BATCH * 10];   // [10][B]
__device__ __align__(16) float g_z7[BATCH * 2];    // [2][B]
__device__ float    g_qw[10113];                   // quantized weights /8 (fc)
__device__ unsigned g_qwp[686];                    // packed s8 conv weights
__device__ double   g_stats[140];

enum { QF1 = 2693, QF2 = 10093 };                       // float weight offsets
enum { P1 = 0, P2 = 6, P3 = 36, P4 = 86, P5 = 286 };    // packed word offsets
enum { S1 = 0, S2 = 6, S3 = 16, S4 = 36, S5 = 76, S6 = 116, S7 = 136 };

__device__ __forceinline__ float qz(float x) {
    x = fminf(fmaxf(x, -1.f), 0.875f);
    return rintf(x * 8.f) * 0.125f;
}
// float q8 (fc path): 8*quantize(x*sc+sh)
__device__ __forceinline__ float q8(float x, float sc8, float sh8) {
    return rintf(fminf(fmaxf(fmaf(x, sc8, sh8), -8.f), 7.f));
}
// int quantizer for staging: round-half-even, clamp to [-8,7]
__device__ __forceinline__ int cq(float x, float sc, float sh) {
    return __float2int_rn(fminf(fmaxf(fmaf(x, sc, sh), -8.f), 7.f));
}
__device__ __forceinline__ unsigned pack4(int b0, int b1, int b2, int b3) {
    unsigned p01 = __byte_perm((unsigned)b0, (unsigned)b1, 0x0040);
    unsigned p23 = __byte_perm((unsigned)b2, (unsigned)b3, 0x0040);
    return __byte_perm(p01, p23, 0x5410);
}
__device__ __forceinline__ int dp4(unsigned a, unsigned b, int c) {
    return __dp4a((int)a, (int)b, c);
}

// ---- prep: float weights (fc) + packed s8 conv weights + zero stats ----
__global__ void prep_kernel(const float* __restrict__ w1, const float* __restrict__ w2,
                            const float* __restrict__ w3, const float* __restrict__ w4,
                            const float* __restrict__ w5, const float* __restrict__ fw1,
                            const float* __restrict__ fw2) {
    int i = blockIdx.x * blockDim.x + threadIdx.x;
    if (i < 140) g_stats[i] = 0.0;
    if (i < 10113) {
        float v;
        if      (i < 18)    v = w1[i];
        else if (i < 93)    v = w2[i - 18];
        else if (i < 293)   v = w3[i - 93];
        else if (i < 1093)  v = w4[i - 293];
        else if (i < 2693)  v = w5[i - 1093];
        else if (i < 10093) v = fw1[i - 2693];
        else                v = fw2[i - 10093];
        g_qw[i] = qz(v) * 0.125f;
    }
    if (i < 686) {
        int base, CI, CO, K;
        const float* src;
        if      (i < 6)   { base = P1;  CI = 1;  CO = 3;  K = 6; src = w1; }
        else if (i < 36)  { base = P2;  CI = 3;  CO = 5;  K = 5; src = w2; }
        else if (i < 86)  { base = P3;  CI = 5;  CO = 10; K = 4; src = w3; }
        else if (i < 286) { base = P4;  CI = 10; CO = 20; K = 4; src = w4; }
        else              { base = P5;  CI = 20; CO = 20; K = 4; src = w5; }
        int idx = i - base;
        int kw = (K + 3) >> 2;
        int t  = idx % kw;
        int co = (idx / kw) % CO;
        int ci = idx / (kw * CO);
        unsigned word = 0;
        for (int k4 = 0; k4 < 4; k4++) {
            int k = t * 4 + k4;
            int b = 0;
            if (k < K) {
                float v = src[(co * CI + ci) * K + k];
                b = (int)rintf(fminf(fmaxf(v, -1.f), 0.875f) * 8.f);
            }
            word |= (unsigned)(b & 0xff) << (8 * k4);
        }
        g_qwp[i] = word;
    }
}

// ---- conv: [B][CIN][SLI] float -> [B][COUT][SLO] float(=64*conv), stride 2 ----
template <int CIN, int SLI, int SLIR, int COUT, int LOUT, int SLO, int KS,
          int SUBS, int GDIV, int LS, int TP, int NGRP, int VST, bool FLAT,
          int NT, int MINB>
__global__ void __launch_bounds__(NT, MINB)
conv_k(const float* __restrict__ xin, int in_sel, int out_sel, int qwp_off,
       const float* __restrict__ gv, const float* __restrict__ bv,
       int prev_st, double invN, int st_off) {
    static_assert(GDIV * LS == NT, "blk");
    constexpr int KW   = (KS + 3) >> 2;
    constexpr int LOP  = (LOUT + 1) & ~1;
    constexpr int NW   = (TP - 2) / 2 + KW + 1;
    constexpr int PW   = (LOP - TP) / 2 + NW + 2;
    constexpr int SBI  = CIN * SLI;
    constexpr int SBO  = COUT * SLO;
    constexpr int CG   = COUT / GDIV;
    constexpr int FROW = 744;
    constexpr int SIN_W  = SUBS * CIN * PW;
    constexpr int SOUT_W = FLAT ? (SUBS * FROW) : (SUBS * SBO);
    constexpr int UNI    = SIN_W > SOUT_W ? SIN_W : SOUT_W;

    __shared__ alignas(16) unsigned s_u[UNI];
    __shared__ alignas(8)  unsigned s_wp[CIN * COUT * KW];
    __shared__ float2 s_aff[CIN];
    __shared__ float  s_sum[COUT], s_sq[COUT];

    const float* in  = (in_sel < 0) ? xin : (in_sel == 0 ? g_bufA : g_bufB);
    float*       out = (out_sel == 0) ? g_bufA : g_bufB;
    const int tid = threadIdx.x;

    for (int i = tid; i < CIN * COUT * KW; i += NT) s_wp[i] = g_qwp[qwp_off + i];
    if (tid < CIN) {
        float2 a;
        if (in_sel < 0) a = make_float2(8.f, 0.f);
        else {
            // stored values are 64*conv
            double mean = g_stats[prev_st + 2 * tid] * invN * 0.015625;
            double msq  = g_stats[prev_st + 2 * tid + 1] * invN * 0.000244140625;
            double var  = msq - mean * mean;
            double s    = (double)gv[tid] / sqrt(var + 1e-5);
            a = make_float2((float)(s * 0.125),
                            (float)(8.0 * ((double)bv[tid] - mean * s)));
        }
        s_aff[tid] = a;
    }
    if (tid < COUT) { s_sum[tid] = 0.f; s_sq[tid] = 0.f; }
    __syncthreads();

    const int b0 = blockIdx.x * SUBS;

    // ---- stage: float -> packed s8 words, one plane per (sub, ci) ----
    for (int i = tid; i < SUBS * CIN * PW; i += NT) {
        int w  = i % PW;
        int pl = i / PW;
        int ci = pl % CIN;
        int sub = pl / CIN;
        float2 a = s_aff[ci];
        unsigned word = 0;
        const float* src = in + (size_t)(b0 + sub) * SBI + ci * SLI + 4 * w;
        if (4 * w + 4 <= SLIR) {
            int q0, q1, q2, q3;
            if (VST == 4) {
                float4 v = *reinterpret_cast<const float4*>(src);
                q0 = cq(v.x, a.x, a.y); q1 = cq(v.y, a.x, a.y);
                q2 = cq(v.z, a.x, a.y); q3 = cq(v.w, a.x, a.y);
            } else {
                float2 v0 = *reinterpret_cast<const float2*>(src);
                float2 v1 = *reinterpret_cast<const float2*>(src + 2);
                q0 = cq(v0.x, a.x, a.y); q1 = cq(v0.y, a.x, a.y);
                q2 = cq(v1.x, a.x, a.y); q3 = cq(v1.y, a.x, a.y);
            }
            word = pack4(q0, q1, q2, q3);
        } else if (4 * w < SLIR) {     // partial tail word (conv1 only)
            float2 v0 = *reinterpret_cast<const float2*>(src);
            word = pack4(cq(v0.x, a.x, a.y), cq(v0.y, a.x, a.y), 0, 0);
        }
        s_u[i] = word;
    }
    __syncthreads();

    // ---- compute ----
    const int g    = tid / LS;
    const int lidx = tid % LS;
    int sub = lidx / NGRP;
    const int grp = lidx - sub * NGRP;
    const bool idle = (sub >= SUBS);
    if (idle) sub = 0;
    const int lb   = grp * TP;
    const int lr   = (lb <= LOP - TP) ? lb : (LOP - TP);   // even
    const int skip = idle ? TP : (lb - lr);
    const int iw0  = lr >> 1;

    int acc[TP][CG];
#pragma unroll
    for (int p = 0; p < TP; p++)
#pragma unroll
        for (int j = 0; j < CG; j++) acc[p][j] = 0;

    const unsigned* inp = s_u + sub * CIN * PW + iw0;
    const unsigned* wp  = s_wp + g * CG * KW;
    for (int ci = 0; ci < CIN; ci++) {
        unsigned W[NW];
#pragma unroll
        for (int t = 0; t < NW; t++) W[t] = inp[t];
        unsigned T[TP][KW];
#pragma unroll
        for (int p = 0; p < TP; p++)
#pragma unroll
            for (int t = 0; t < KW; t++)
                T[p][t] = (p & 1)
                    ? __byte_perm(W[((p - 1) >> 1) + t], W[((p - 1) >> 1) + t + 1], 0x5432)
                    : W[(p >> 1) + t];
#pragma unroll
        for (int j = 0; j < CG; j++) {
#pragma unroll
            for (int t = 0; t < KW; t++) {
                unsigned wv = wp[j * KW + t];
#pragma unroll
                for (int p = 0; p < TP; p++)
                    acc[p][j] = dp4(T[p][t], wv, acc[p][j]);
            }
        }
        inp += PW;
        wp  += COUT * KW;
    }
    __syncthreads();   // s_in reads done; s_u becomes s_out (float bits)

    // ---- store + stats ----
    float lsum[CG], lsq[CG];
#pragma unroll
    for (int j = 0; j < CG; j++) { lsum[j] = 0.f; lsq[j] = 0.f; }
#pragma unroll
    for (int p = 0; p < TP; p++) {
        int l = lr + p;
        if (p >= skip && l < LOUT) {
#pragma unroll
            for (int j = 0; j < CG; j++) {
                float v = (float)acc[p][j];        // exact: 64*conv
                int co = g * CG + j;
                int idx = FLAT ? (sub * FROW + co * LOUT + l)
                               : ((sub * COUT + co) * SLO + l);
                s_u[idx] = __float_as_uint(v);
                lsum[j] += v;
                lsq[j] = fmaf(v, v, lsq[j]);
            }
        }
    }
    // warps are g-uniform (LS multiple of 32): full-warp shuffle reduce
#pragma unroll
    for (int j = 0; j < CG; j++) {
        float vs = lsum[j], vq = lsq[j];
#pragma unroll
        for (int o = 16; o > 0; o >>= 1) {
            vs += __shfl_xor_sync(0xffffffffu, vs, o);
            vq += __shfl_xor_sync(0xffffffffu, vq, o);
        }
        if ((tid & 31) == 0) {
            atomicAdd(&s_sum[g * CG + j], vs);
            atomicAdd(&s_sq[g * CG + j], vq);
        }
    }
    __syncthreads();

    // ---- output sweep ----
    if (FLAT) {
        for (int i = tid; i < SUBS * 740; i += NT) {
            int bb = i & (SUBS - 1);
            int f  = i / SUBS;
            out[(size_t)f * BATCH + b0 + bb] = __uint_as_float(s_u[bb * FROW + f]);
        }
    } else {
        constexpr int WPS = (NT / 32) / SUBS;    // warps per slab
        const int wid = tid >> 5, lane = tid & 31;
        const int slab = wid / WPS;
        const int r0 = (wid % WPS) * 32 + lane;
        const float4* sv = reinterpret_cast<const float4*>(s_u) + slab * (SBO / 4);
        float4* gp = reinterpret_cast<float4*>(out + (size_t)(b0 + slab) * SBO);
        for (int r = r0; r < SBO / 4; r += WPS * 32) gp[r] = sv[r];
    }

    if (tid < COUT) {
        atomicAdd(&g_stats[st_off + 2 * tid],     (double)s_sum[tid]);
        atomicAdd(&g_stats[st_off + 2 * tid + 1], (double)s_sq[tid]);
    }
}

// ---- FC1: z6[j][b], input [740][B] float(=64*conv) ----
__global__ void __launch_bounds__(256)
fc1_kernel(const float* __restrict__ gv, const float* __restrict__ bv) {
    __shared__ float  sw[7400];        // [f][j]
    __shared__ float2 saff[740];
    __shared__ float2 schan[20];
    __shared__ float  sp[8][32][10];
    __shared__ float  ssum[10], ssq[10];
    const int tid = threadIdx.x;

    for (int i = tid; i < 7400; i += 256) {
        int f = i / 10, j = i - f * 10;
        sw[i] = g_qw[QF1 + j * 740 + f];
    }
    if (tid < 20) {
        const double invN = 1.0 / (8192.0 * 37.0);
        double mean = g_stats[S5 + 2 * tid] * invN * 0.015625;
        double msq  = g_stats[S5 + 2 * tid + 1] * invN * 0.000244140625;
        double var  = msq - mean * mean;
        double s    = (double)gv[tid] / sqrt(var + 1e-5);
        schan[tid] = make_float2((float)(s * 0.125),
                                 (float)(8.0 * ((double)bv[tid] - mean * s)));
    }
    if (tid < 10) { ssum[tid] = 0.f; ssq[tid] = 0.f; }
    __syncthreads();
    for (int f = tid; f < 740; f += 256) saff[f] = schan[f / 37];
    __syncthreads();

    const int bl    = tid & 31;
    const int chunk = tid >> 5;
    const int b     = blockIdx.x * 32 + bl;
    const int fs = chunk * 92 + (chunk < 4 ? chunk : 4);
    const int fe = fs + (chunk < 4 ? 93 : 92);

    float acc[10];
#pragma unroll
    for (int j = 0; j < 10; j++) acc[j] = 0.f;
    for (int f = fs; f < fe; f++) {
        float2 af = saff[f];
        float a = q8(g_bufA[(size_t)f * BATCH + b], af.x, af.y);
        const float* wr = &sw[f * 10];
#pragma unroll
        for (int j = 0; j < 10; j++) acc[j] = fmaf(a, wr[j], acc[j]);
    }
#pragma unroll
    for (int j = 0; j < 10; j++) sp[chunk][bl][j] = acc[j];
    __syncthreads();

    for (int i = tid; i < 320; i += 256) {
        int b2 = i / 10, j = i - b2 * 10;
        float t = 0.f;
#pragma unroll
        for (int ch = 0; ch < 8; ch++) t += sp[ch][b2][j];
        g_z6[(size_t)j * BATCH + blockIdx.x * 32 + b2] = t;
        atomicAdd(&ssum[j], t);
        atomicAdd(&ssq[j], t * t);
    }
    __syncthreads();
    if (tid < 10) {
        atomicAdd(&g_stats[S6 + 2 * tid],     (double)ssum[tid]);
        atomicAdd(&g_stats[S6 + 2 * tid + 1], (double)ssq[tid]);
    }
}

// ---- FC2: z7[c][b] ----
__global__ void __launch_bounds__(256)
fc2_kernel(const float* __restrict__ gv, const float* __restrict__ bv) {
    __shared__ float  sw[20];
    __shared__ float2 saff[10];
    __shared__ float  ssum[2], ssq[2];
    const int tid = threadIdx.x;
    if (tid < 20) sw[tid] = g_qw[QF2 + tid];
    if (tid < 10) {
        const double invN = 1.0 / 8192.0;
        double mean = g_stats[S6 + 2 * tid] * invN;
        double var  = g_stats[S6 + 2 * tid + 1] * invN - mean * mean;
        double s    = (double)gv[tid] / sqrt(var + 1e-5);
        saff[tid] = make_float2((float)(8.0 * s), (float)(8.0 * ((double)bv[tid] - mean * s)));
    }
    if (tid < 2) { ssum[tid] = 0.f; ssq[tid] = 0.f; }
    __syncthreads();

    const int b = blockIdx.x * 256 + tid;
    float a0 = 0.f, a1 = 0.f;
#pragma unroll
    for (int j = 0; j < 10; j++) {
        float a = q8(g_z6[(size_t)j * BATCH + b], saff[j].x, saff[j].y);
        a0 = fmaf(a, sw[j], a0);
        a1 = fmaf(a, sw[10 + j], a1);
    }
    g_z7[b]         = a0;
    g_z7[BATCH + b] = a1;

    float s0 = a0, q0 = a0 * a0, s1 = a1, q1 = a1 * a1;
#pragma unroll
    for (int o = 16; o > 0; o >>= 1) {
        s0 += __shfl_xor_sync(0xffffffffu, s0, o);
        q0 += __shfl_xor_sync(0xffffffffu, q0, o);
        s1 += __shfl_xor_sync(0xffffffffu, s1, o);
        q1 += __shfl_xor_sync(0xffffffffu, q1, o);
    }
    if ((tid & 31) == 0) {
        atomicAdd(&ssum[0], s0); atomicAdd(&ssq[0], q0);
        atomicAdd(&ssum[1], s1); atomicAdd(&ssq[1], q1);
    }
    __syncthreads();
    if (tid < 2) {
        atomicAdd(&g_stats[S7 + 2 * tid],     (double)ssum[tid]);
        atomicAdd(&g_stats[S7 + 2 * tid + 1], (double)ssq[tid]);
    }
}

// ---- final: out[b][c] = bn7(z7) ----
__global__ void final_kernel(const float* __restrict__ gv, const float* __restrict__ bv,
                             float* __restrict__ out) {
    const int b = blockIdx.x * blockDim.x + threadIdx.x;
    if (b < BATCH) {
        const double invN = 1.0 / 8192.0;
        float o[2];
#pragma unroll
        for (int c = 0; c < 2; c++) {
            double mean = g_stats[S7 + 2 * c] * invN;
            double var  = g_stats[S7 + 2 * c + 1] * invN - mean * mean;
            double s    = (double)gv[c] / sqrt(var + 1e-5);
            o[c] = (float)(((double)g_z7[c * BATCH + b] - mean) * s + (double)bv[c]);
        }
        *reinterpret_cast<float2*>(&out[b * 2]) = make_float2(o[0], o[1]);
    }
}

extern "C" void kernel_launch(void* const* d_in, const int* in_sizes, int n_in,
                              void* d_out, int out_size) {
    const float* x   = (const float*)d_in[0];
    const float* w1  = (const float*)d_in[1];
    const float* w2  = (const float*)d_in[2];
    const float* w3  = (const float*)d_in[3];
    const float* w4  = (const float*)d_in[4];
    const float* w5  = (const float*)d_in[5];
    const float* fw1 = (const float*)d_in[6];
    const float* fw2 = (const float*)d_in[7];

    bool inter = (in_sizes[9] == 3);
    const float *gg[7], *bb[7];
    for (int i = 0; i < 7; i++) {
        if (inter) { gg[i] = (const float*)d_in[8 + 2 * i]; bb[i] = (const float*)d_in[9 + 2 * i]; }
        else       { gg[i] = (const float*)d_in[8 + i];     bb[i] = (const float*)d_in[15 + i];    }
    }
    float* out = (float*)d_out;

    const double iN1 = 1.0 / (8192.0 * 623.0), iN2 = 1.0 / (8192.0 * 310.0);
    const double iN3 = 1.0 / (8192.0 * 154.0), iN4 = 1.0 / (8192.0 * 76.0);

    prep_kernel<<<40, 256>>>(w1, w2, w3, w4, w5, fw1, fw2);

    // conv1: x[B][1][1250] -> A[B][3][624]   SUBS=2, LS=128, TP=10, NGRP=63
    conv_k<1, 1250, 1250, 3, 623, 624, 6, 2, 1, 128, 10, 63, 2, false, 128, 4>
        <<<4096, 128>>>(x, -1, 0, P1, x, x, 0, 0.0, S1);
    // conv2: A[B][3][624] -> B[B][5][312]    SUBS=4, LS=128, TP=10, NGRP=31
    conv_k<3, 624, 624, 5, 310, 312, 5, 4, 1, 128, 10, 31, 4, false, 128, 4>
        <<<2048, 128>>>(x, 0, 1, P2, gg[0], bb[0], S1, iN1, S2);
    // conv3: B[B][5][312] -> A[B][10][156]   SUBS=4, GDIV=2, LS=128, TP=6, NGRP=26
    conv_k<5, 312, 312, 10, 154, 156, 4, 4, 2, 128, 6, 26, 4, false, 256, 3>
        <<<2048, 256>>>(x, 1, 0, P3, gg[1], bb[1], S2, iN2, S3);
    // conv4: A[B][10][156] -> B[B][20][76]   SUBS=4, GDIV=4, LS=96, TP=4, NGRP=19
    conv_k<10, 156, 156, 20, 76, 76, 4, 4, 4, 96, 4, 19, 4, false, 384, 2>
        <<<2048, 384>>>(x, 0, 1, P4, gg[2], bb[2], S3, iN3, S4);
    // conv5: B[B][20][76] -> A[740][B] flat  SUBS=8, GDIV=4, LS=160, TP=2, NGRP=19
    conv_k<20, 76, 76, 20, 37, 40, 4, 8, 4, 160, 2, 19, 4, true, 640, 2>
        <<<1024, 640>>>(x, 1, 0, P5, gg[3], bb[3], S4, iN4, S5);

    fc1_kernel<<<256, 256>>>(gg[4], bb[4]);
    fc2_kernel<<<32, 256>>>(gg[5], bb[5]);
    final_kernel<<<32, 256>>>(gg[6], bb[6], out);
}

// round 17
// speedup vs baseline: 10.2472x; 1.1191x over previous
#include <cuda_runtime.h>

// ============================================================================
// IEGMNetXNORNew — R17: R16 dp4a core + int16 activation storage.
// All inter-layer activations are exact s16 (|64*conv| <= 5120): halves HBM/
// L2/L1 traffic, staging loads (short4), and output sweeps (uint4 = 8 vals).
// Consumer BN affine folding unchanged (stored = 64*conv). Padded SLO keeps
// 8B alignment; buffers have slack for window over-read.
// ============================================================================

#define BATCH 8192

__device__ __align__(16) short g_sA[15343616];   // B*1872 + slack
__device__ __align__(16) short g_sB[13115392];   // B*1600 + slack
__device__ __align__(16) float g_z6[BATCH * 10]; // [10][B]
__device__ __align__(16) float g_z7[BATCH * 2];  // [2][B]
__device__ float    g_qw[10113];                 // quantized weights /8 (fc)
__device__ unsigned g_qwp[686];                  // packed s8 conv weights
__device__ double   g_stats[140];

enum { QF1 = 2693, QF2 = 10093 };
enum { P1 = 0, P2 = 6, P3 = 36, P4 = 86, P5 = 286 };
enum { S1 = 0, S2 = 6, S3 = 16, S4 = 36, S5 = 76, S6 = 116, S7 = 136 };

__device__ __forceinline__ float qz(float x) {
    x = fminf(fmaxf(x, -1.f), 0.875f);
    return rintf(x * 8.f) * 0.125f;
}
__device__ __forceinline__ float q8(float x, float sc8, float sh8) {
    return rintf(fminf(fmaxf(fmaf(x, sc8, sh8), -8.f), 7.f));
}
__device__ __forceinline__ int cq(float x, float sc, float sh) {
    return __float2int_rn(fminf(fmaxf(fmaf(x, sc, sh), -8.f), 7.f));
}
__device__ __forceinline__ unsigned pack4(int b0, int b1, int b2, int b3) {
    unsigned p01 = __byte_perm((unsigned)b0, (unsigned)b1, 0x0040);
    unsigned p23 = __byte_perm((unsigned)b2, (unsigned)b3, 0x0040);
    return __byte_perm(p01, p23, 0x5410);
}
__device__ __forceinline__ int dp4(unsigned a, unsigned b, int c) {
    return __dp4a((int)a, (int)b, c);
}

// ---- prep ----
__global__ void prep_kernel(const float* __restrict__ w1, const float* __restrict__ w2,
                            const float* __restrict__ w3, const float* __restrict__ w4,
                            const float* __restrict__ w5, const float* __restrict__ fw1,
                            const float* __restrict__ fw2) {
    int i = blockIdx.x * blockDim.x + threadIdx.x;
    if (i < 140) g_stats[i] = 0.0;
    if (i < 10113) {
        float v;
        if      (i < 18)    v = w1[i];
        else if (i < 93)    v = w2[i - 18];
        else if (i < 293)   v = w3[i - 93];
        else if (i < 1093)  v = w4[i - 293];
        else if (i < 2693)  v = w5[i - 1093];
        else if (i < 10093) v = fw1[i - 2693];
        else                v = fw2[i - 10093];
        g_qw[i] = qz(v) * 0.125f;
    }
    if (i < 686) {
        int base, CI, CO, K;
        const float* src;
        if      (i < 6)   { base = P1;  CI = 1;  CO = 3;  K = 6; src = w1; }
        else if (i < 36)  { base = P2;  CI = 3;  CO = 5;  K = 5; src = w2; }
        else if (i < 86)  { base = P3;  CI = 5;  CO = 10; K = 4; src = w3; }
        else if (i < 286) { base = P4;  CI = 10; CO = 20; K = 4; src = w4; }
        else              { base = P5;  CI = 20; CO = 20; K = 4; src = w5; }
        int idx = i - base;
        int kw = (K + 3) >> 2;
        int t  = idx % kw;
        int co = (idx / kw) % CO;
        int ci = idx / (kw * CO);
        unsigned word = 0;
        for (int k4 = 0; k4 < 4; k4++) {
            int k = t * 4 + k4;
            int b = 0;
            if (k < K) {
                float v = src[(co * CI + ci) * K + k];
                b = (int)rintf(fminf(fmaxf(v, -1.f), 0.875f) * 8.f);
            }
            word |= (unsigned)(b & 0xff) << (8 * k4);
        }
        g_qwp[i] = word;
    }
}

// ---- conv: s16 (or float for conv1) [B][CIN][SLI] -> s16 [B][COUT][SLO] ----
template <int CIN, int SLI, int SLIR, int COUT, int LOUT, int SLO, int KS,
          int SUBS, int GDIV, int LS, int TP, int NGRP, bool ISF, bool FLAT,
          int NT, int MINB>
__global__ void __launch_bounds__(NT, MINB)
conv_k(const float* __restrict__ xin, int in_sel, int out_sel, int qwp_off,
       const float* __restrict__ gv, const float* __restrict__ bv,
       int prev_st, double invN, int st_off) {
    static_assert(GDIV * LS == NT, "blk");
    constexpr int KW   = (KS + 3) >> 2;
    constexpr int LOP  = (LOUT + 1) & ~1;
    constexpr int NW   = (TP - 2) / 2 + KW + 1;
    constexpr int PW   = (LOP - TP) / 2 + NW + 2;
    constexpr int SBI  = CIN * SLI;
    constexpr int SBO  = COUT * SLO;
    constexpr int CG   = COUT / GDIV;
    constexpr int FROW = 744;
    constexpr int SIN_W  = SUBS * CIN * PW;
    constexpr int SOUT_W = FLAT ? (SUBS * FROW / 2) : (SUBS * SBO / 2);  // s16
    constexpr int UNI    = SIN_W > SOUT_W ? SIN_W : SOUT_W;

    __shared__ alignas(16) unsigned s_u[UNI];
    __shared__ alignas(8)  unsigned s_wp[CIN * COUT * KW];
    __shared__ float2 s_aff[CIN];
    __shared__ float  s_sum[COUT], s_sq[COUT];

    const short* sin = (in_sel == 0) ? g_sA : g_sB;
    short*       out = (out_sel == 0) ? g_sA : g_sB;
    const int tid = threadIdx.x;

    for (int i = tid; i < CIN * COUT * KW; i += NT) s_wp[i] = g_qwp[qwp_off + i];
    if (tid < CIN) {
        float2 a;
        if (ISF) a = make_float2(8.f, 0.f);
        else {
            // stored values are 64*conv
            double mean = g_stats[prev_st + 2 * tid] * invN * 0.015625;
            double msq  = g_stats[prev_st + 2 * tid + 1] * invN * 0.000244140625;
            double var  = msq - mean * mean;
            double s    = (double)gv[tid] / sqrt(var + 1e-5);
            a = make_float2((float)(s * 0.125),
                            (float)(8.0 * ((double)bv[tid] - mean * s)));
        }
        s_aff[tid] = a;
    }
    if (tid < COUT) { s_sum[tid] = 0.f; s_sq[tid] = 0.f; }
    __syncthreads();

    const int b0 = blockIdx.x * SUBS;

    // ---- stage: -> packed s8 words ----
    for (int i = tid; i < SUBS * CIN * PW; i += NT) {
        int w  = i % PW;
        int pl = i / PW;
        int ci = pl % CIN;
        int sub = pl / CIN;
        float2 a = s_aff[ci];
        unsigned word = 0;
        if (ISF) {
            const float* src = xin + (size_t)(b0 + sub) * SBI + ci * SLI + 4 * w;
            if (4 * w + 4 <= SLIR) {
                float2 v0 = *reinterpret_cast<const float2*>(src);
                float2 v1 = *reinterpret_cast<const float2*>(src + 2);
                word = pack4(cq(v0.x, a.x, a.y), cq(v0.y, a.x, a.y),
                             cq(v1.x, a.x, a.y), cq(v1.y, a.x, a.y));
            } else if (4 * w < SLIR) {
                float2 v0 = *reinterpret_cast<const float2*>(src);
                word = pack4(cq(v0.x, a.x, a.y), cq(v0.y, a.x, a.y), 0, 0);
            }
        } else {
            const short4 v = *reinterpret_cast<const short4*>(
                sin + (size_t)(b0 + sub) * SBI + ci * SLI + 4 * w);
            word = pack4(cq((float)v.x, a.x, a.y), cq((float)v.y, a.x, a.y),
                         cq((float)v.z, a.x, a.y), cq((float)v.w, a.x, a.y));
        }
        s_u[i] = word;
    }
    __syncthreads();

    // ---- compute ----
    const int g    = tid / LS;
    const int lidx = tid % LS;
    int sub = lidx / NGRP;
    const int grp = lidx - sub * NGRP;
    const bool idle = (sub >= SUBS);
    if (idle) sub = 0;
    const int lb   = grp * TP;
    const int lr   = (lb <= LOP - TP) ? lb : (LOP - TP);   // even
    const int skip = idle ? TP : (lb - lr);
    const int iw0  = lr >> 1;

    int acc[TP][CG];
#pragma unroll
    for (int p = 0; p < TP; p++)
#pragma unroll
        for (int j = 0; j < CG; j++) acc[p][j] = 0;

    const unsigned* inp = s_u + sub * CIN * PW + iw0;
    const unsigned* wp  = s_wp + g * CG * KW;
    for (int ci = 0; ci < CIN; ci++) {
        unsigned W[NW];
#pragma unroll
        for (int t = 0; t < NW; t++) W[t] = inp[t];
        unsigned T[TP][KW];
#pragma unroll
        for (int p = 0; p < TP; p++)
#pragma unroll
            for (int t = 0; t < KW; t++)
                T[p][t] = (p & 1)
                    ? __byte_perm(W[((p - 1) >> 1) + t], W[((p - 1) >> 1) + t + 1], 0x5432)
                    : W[(p >> 1) + t];
#pragma unroll
        for (int j = 0; j < CG; j++) {
#pragma unroll
            for (int t = 0; t < KW; t++) {
                unsigned wv = wp[j * KW + t];
#pragma unroll
                for (int p = 0; p < TP; p++)
                    acc[p][j] = dp4(T[p][t], wv, acc[p][j]);
            }
        }
        inp += PW;
        wp  += COUT * KW;
    }
    __syncthreads();   // s_in reads done; s_u becomes s_out (s16)

    short* s_o = reinterpret_cast<short*>(s_u);

    // ---- store + stats ----
    float lsum[CG], lsq[CG];
#pragma unroll
    for (int j = 0; j < CG; j++) { lsum[j] = 0.f; lsq[j] = 0.f; }
#pragma unroll
    for (int p = 0; p < TP; p++) {
        int l = lr + p;
        if (p >= skip && l < LOUT) {
#pragma unroll
            for (int j = 0; j < CG; j++) {
                int av = acc[p][j];                 // exact: 64*conv, |av|<=5120
                float v = (float)av;
                int co = g * CG + j;
                int idx = FLAT ? (sub * FROW + co * LOUT + l)
                               : ((sub * COUT + co) * SLO + l);
                s_o[idx] = (short)av;
                lsum[j] += v;
                lsq[j] = fmaf(v, v, lsq[j]);
            }
        }
    }
    // warps g-uniform: full-warp shuffle reduce
#pragma unroll
    for (int j = 0; j < CG; j++) {
        float vs = lsum[j], vq = lsq[j];
#pragma unroll
        for (int o = 16; o > 0; o >>= 1) {
            vs += __shfl_xor_sync(0xffffffffu, vs, o);
            vq += __shfl_xor_sync(0xffffffffu, vq, o);
        }
        if ((tid & 31) == 0) {
            atomicAdd(&s_sum[g * CG + j], vs);
            atomicAdd(&s_sq[g * CG + j], vq);
        }
    }
    __syncthreads();

    // ---- output sweep ----
    if (FLAT) {
        for (int i = tid; i < SUBS * 740; i += NT) {
            int bb = i & (SUBS - 1);
            int f  = i / SUBS;
            out[(size_t)f * BATCH + b0 + bb] = s_o[bb * FROW + f];
        }
    } else {
        constexpr int WPS = (NT / 32) / SUBS;    // warps per slab
        const int wid = tid >> 5, lane = tid & 31;
        const int slab = wid / WPS;
        const int r0 = (wid % WPS) * 32 + lane;
        const uint4* sv = reinterpret_cast<const uint4*>(s_u) + slab * (SBO / 8);
        uint4* gp = reinterpret_cast<uint4*>(out + (size_t)(b0 + slab) * SBO);
        for (int r = r0; r < SBO / 8; r += WPS * 32) gp[r] = sv[r];
    }

    if (tid < COUT) {
        atomicAdd(&g_stats[st_off + 2 * tid],     (double)s_sum[tid]);
        atomicAdd(&g_stats[st_off + 2 * tid + 1], (double)s_sq[tid]);
    }
}

// ---- FC1: z6[j][b], input s16 [740][B] (=64*conv) ----
__global__ void __launch_bounds__(256)
fc1_kernel(const float* __restrict__ gv, const float* __restrict__ bv) {
    __shared__ float  sw[7400];        // [f][j]
    __shared__ float2 saff[740];
    __shared__ float2 schan[20];
    __shared__ float  sp[8][32][10];
    __shared__ float  ssum[10], ssq[10];
    const int tid = threadIdx.x;

    for (int i = tid; i < 7400; i += 256) {
        int f = i / 10, j = i - f * 10;
        sw[i] = g_qw[QF1 + j * 740 + f];
    }
    if (tid < 20) {
        const double invN = 1.0 / (8192.0 * 37.0);
        double mean = g_stats[S5 + 2 * tid] * invN * 0.015625;
        double msq  = g_stats[S5 + 2 * tid + 1] * invN * 0.000244140625;
        double var  = msq - mean * mean;
        double s    = (double)gv[tid] / sqrt(var + 1e-5);
        schan[tid] = make_float2((float)(s * 0.125),
                                 (float)(8.0 * ((double)bv[tid] - mean * s)));
    }
    if (tid < 10) { ssum[tid] = 0.f; ssq[tid] = 0.f; }
    __syncthreads();
    for (int f = tid; f < 740; f += 256) saff[f] = schan[f / 37];
    __syncthreads();

    const int bl    = tid & 31;
    const int chunk = tid >> 5;
    const int b     = blockIdx.x * 32 + bl;
    const int fs = chunk * 92 + (chunk < 4 ? chunk : 4);
    const int fe = fs + (chunk < 4 ? 93 : 92);

    float acc[10];
#pragma unroll
    for (int j = 0; j < 10; j++) acc[j] = 0.f;
    for (int f = fs; f < fe; f++) {
        float2 af = saff[f];
        float a = q8((float)g_sA[(size_t)f * BATCH + b], af.x, af.y);
        const float* wr = &sw[f * 10];
#pragma unroll
        for (int j = 0; j < 10; j++) acc[j] = fmaf(a, wr[j], acc[j]);
    }
#pragma unroll
    for (int j = 0; j < 10; j++) sp[chunk][bl][j] = acc[j];
    __syncthreads();

    for (int i = tid; i < 320; i += 256) {
        int b2 = i / 10, j = i - b2 * 10;
        float t = 0.f;
#pragma unroll
        for (int ch = 0; ch < 8; ch++) t += sp[ch][b2][j];
        g_z6[(size_t)j * BATCH + blockIdx.x * 32 + b2] = t;
        atomicAdd(&ssum[j], t);
        atomicAdd(&ssq[j], t * t);
    }
    __syncthreads();
    if (tid < 10) {
        atomicAdd(&g_stats[S6 + 2 * tid],     (double)ssum[tid]);
        atomicAdd(&g_stats[S6 + 2 * tid + 1], (double)ssq[tid]);
    }
}

// ---- FC2: z7[c][b] ----
__global__ void __launch_bounds__(256)
fc2_kernel(const float* __restrict__ gv, const float* __restrict__ bv) {
    __shared__ float  sw[20];
    __shared__ float2 saff[10];
    __shared__ float  ssum[2], ssq[2];
    const int tid = threadIdx.x;
    if (tid < 20) sw[tid] = g_qw[QF2 + tid];
    if (tid < 10) {
        const double invN = 1.0 / 8192.0;
        double mean = g_stats[S6 + 2 * tid] * invN;
        double var  = g_stats[S6 + 2 * tid + 1] * invN - mean * mean;
        double s    = (double)gv[tid] / sqrt(var + 1e-5);
        saff[tid] = make_float2((float)(8.0 * s), (float)(8.0 * ((double)bv[tid] - mean * s)));
    }
    if (tid < 2) { ssum[tid] = 0.f; ssq[tid] = 0.f; }
    __syncthreads();

    const int b = blockIdx.x * 256 + tid;
    float a0 = 0.f, a1 = 0.f;
#pragma unroll
    for (int j = 0; j < 10; j++) {
        float a = q8(g_z6[(size_t)j * BATCH + b], saff[j].x, saff[j].y);
        a0 = fmaf(a, sw[j], a0);
        a1 = fmaf(a, sw[10 + j], a1);
    }
    g_z7[b]         = a0;
    g_z7[BATCH + b] = a1;

    float s0 = a0, q0 = a0 * a0, s1 = a1, q1 = a1 * a1;
#pragma unroll
    for (int o = 16; o > 0; o >>= 1) {
        s0 += __shfl_xor_sync(0xffffffffu, s0, o);
        q0 += __shfl_xor_sync(0xffffffffu, q0, o);
        s1 += __shfl_xor_sync(0xffffffffu, s1, o);
        q1 += __shfl_xor_sync(0xffffffffu, q1, o);
    }
    if ((tid & 31) == 0) {
        atomicAdd(&ssum[0], s0); atomicAdd(&ssq[0], q0);
        atomicAdd(&ssum[1], s1); atomicAdd(&ssq[1], q1);
    }
    __syncthreads();
    if (tid < 2) {
        atomicAdd(&g_stats[S7 + 2 * tid],     (double)ssum[tid]);
        atomicAdd(&g_stats[S7 + 2 * tid + 1], (double)ssq[tid]);
    }
}

// ---- final ----
__global__ void final_kernel(const float* __restrict__ gv, const float* __restrict__ bv,
                             float* __restrict__ out) {
    const int b = blockIdx.x * blockDim.x + threadIdx.x;
    if (b < BATCH) {
        const double invN = 1.0 / 8192.0;
        float o[2];
#pragma unroll
        for (int c = 0; c < 2; c++) {
            double mean = g_stats[S7 + 2 * c] * invN;
            double var  = g_stats[S7 + 2 * c + 1] * invN - mean * mean;
            double s    = (double)gv[c] / sqrt(var + 1e-5);
            o[c] = (float)(((double)g_z7[c * BATCH + b] - mean) * s + (double)bv[c]);
        }
        *reinterpret_cast<float2*>(&out[b * 2]) = make_float2(o[0], o[1]);
    }
}

extern "C" void kernel_launch(void* const* d_in, const int* in_sizes, int n_in,
                              void* d_out, int out_size) {
    const float* x   = (const float*)d_in[0];
    const float* w1  = (const float*)d_in[1];
    const float* w2  = (const float*)d_in[2];
    const float* w3  = (const float*)d_in[3];
    const float* w4  = (const float*)d_in[4];
    const float* w5  = (const float*)d_in[5];
    const float* fw1 = (const float*)d_in[6];
    const float* fw2 = (const float*)d_in[7];

    bool inter = (in_sizes[9] == 3);
    const float *gg[7], *bb[7];
    for (int i = 0; i < 7; i++) {
        if (inter) { gg[i] = (const float*)d_in[8 + 2 * i]; bb[i] = (const float*)d_in[9 + 2 * i]; }
        else       { gg[i] = (const float*)d_in[8 + i];     bb[i] = (const float*)d_in[15 + i];    }
    }
    float* out = (float*)d_out;

    const double iN1 = 1.0 / (8192.0 * 623.0), iN2 = 1.0 / (8192.0 * 310.0);
    const double iN3 = 1.0 / (8192.0 * 154.0), iN4 = 1.0 / (8192.0 * 76.0);

    prep_kernel<<<40, 256>>>(w1, w2, w3, w4, w5, fw1, fw2);

    // conv1: x[B][1][1250] f32 -> sA[B][3][624]
    conv_k<1, 1250, 1250, 3, 623, 624, 6, 2, 1, 128, 10, 63, true, false, 128, 4>
        <<<4096, 128>>>(x, -1, 0, P1, x, x, 0, 0.0, S1);
    // conv2: sA[B][3][624] -> sB[B][5][312]
    conv_k<3, 624, 624, 5, 310, 312, 5, 4, 1, 128, 10, 31, false, false, 128, 4>
        <<<2048, 128>>>(x, 0, 1, P2, gg[0], bb[0], S1, iN1, S2);
    // conv3: sB[B][5][312] -> sA[B][10][160]
    conv_k<5, 312, 312, 10, 154, 160, 4, 4, 2, 128, 6, 26, false, false, 256, 4>
        <<<2048, 256>>>(x, 1, 0, P3, gg[1], bb[1], S2, iN2, S3);
    // conv4: sA[B][10][160] -> sB[B][20][80]
    conv_k<10, 160, 160, 20, 76, 80, 4, 4, 4, 96, 4, 19, false, false, 384, 2>
        <<<2048, 384>>>(x, 0, 1, P4, gg[2], bb[2], S3, iN3, S4);
    // conv5: sB[B][20][80] -> sA[740][B] flat
    conv_k<20, 80, 80, 20, 37, 40, 4, 8, 4, 160, 2, 19, false, true, 640, 2>
        <<<1024, 640>>>(x, 1, 0, P5, gg[3], bb[3], S4, iN4, S5);

    fc1_kernel<<<256, 256>>>(gg[4], bb[4]);
    fc2_kernel<<<32, 256>>>(gg[5], bb[5]);
    final_kernel<<<32, 256>>>(gg[6], bb[6], out);
}